// round 4
// baseline (speedup 1.0000x reference)
#include <cuda_runtime.h>

// Problem constants
#define B_  2
#define S_  4096
#define H_  512
#define NH_ 8
#define HD_ 64
#define XSZ (B_ * S_ * H_)                       // 4,194,304 floats (x output)
#define ASZ ((long)B_ * NH_ * S_ * S_)           // 268,435,456 floats (attention output)

// Scratch (device globals: the sanctioned allocation-free workaround)
__device__ float g_Q[B_ * NH_ * S_ * HD_];       // head-split Q  [B,NH,S,HD]
__device__ float g_K[B_ * NH_ * S_ * HD_];       // head-split K
__device__ float g_V[B_ * NH_ * S_ * HD_];       // head-split V
__device__ float g_ctx[B_ * S_ * H_];            // attn @ V, merged heads [B,S,H]
__device__ float g_attn_fb[(long)B_ * NH_ * S_ * S_]; // fallback if d_out lacks attention

// ---------------------------------------------------------------------------
// Generic tiled GEMM: C[M,N] = scale * (A x B) + bias
//   A is [M,K] row-major (K contiguous).
//   If BNT:  B is [N,K] row-major (NT GEMM, e.g. x @ W^T, Q @ K^T)
//   else:    B is [K,N] row-major (NN GEMM, e.g. attn @ V)
//   Tiles: 64x64, depth BK. 256 threads, 4x4 microtile per thread.
//   Smem tiles stored k-major with stride 68 (16B-aligned rows, conflict-free
//   LDS.128 in the compute loop).
//   OUTMODE 0: plain row-major C[m*ldc + n]
//   OUTMODE 1: head-split  (token row m, feature col n) -> [B,NH,S,HD]
//   OUTMODE 2: per-head (z=b*NH+h) AV result merged into [B,S,H]
//   All dims must be multiples of the tile sizes (true for this problem).
// ---------------------------------------------------------------------------
template<int BK, bool BNT, int OUTMODE>
__global__ void __launch_bounds__(256) gemm_k(
    const float* __restrict__ A, const float* __restrict__ Bm,
    const float* __restrict__ bias, float* __restrict__ C,
    int M, int N, int K, int lda, int ldb, int ldc,
    long sAz, long sBz, long sCz, float scale)
{
    __shared__ __align__(16) float As[BK][68];
    __shared__ __align__(16) float Bs[BK][68];

    const int z = blockIdx.z;
    A  += (long)z * sAz;
    Bm += (long)z * sBz;
    C  += (long)z * sCz;

    const int m0 = blockIdx.y * 64;
    const int n0 = blockIdx.x * 64;
    const int t  = threadIdx.x;
    const int tx = t & 15;        // output col group
    const int ty = t >> 4;        // output row group
    const int lrow = t >> 2;      // loader: row within 64 (A and NT-B)
    const int lfb  = t & 3;       // loader: float4 phase

    float acc[4][4] = {};

    for (int k0 = 0; k0 < K; k0 += BK) {
        // --- load A tile (transpose to k-major) ---
        #pragma unroll
        for (int s = 0; s < BK / 16; ++s) {
            const int f4 = lfb + 4 * s;
            float4 v = *(const float4*)(A + (long)(m0 + lrow) * lda + k0 + f4 * 4);
            As[f4*4 + 0][lrow] = v.x;
            As[f4*4 + 1][lrow] = v.y;
            As[f4*4 + 2][lrow] = v.z;
            As[f4*4 + 3][lrow] = v.w;
        }
        // --- load B tile ---
        if (BNT) {
            #pragma unroll
            for (int s = 0; s < BK / 16; ++s) {
                const int f4 = lfb + 4 * s;
                float4 v = *(const float4*)(Bm + (long)(n0 + lrow) * ldb + k0 + f4 * 4);
                Bs[f4*4 + 0][lrow] = v.x;
                Bs[f4*4 + 1][lrow] = v.y;
                Bs[f4*4 + 2][lrow] = v.z;
                Bs[f4*4 + 3][lrow] = v.w;
            }
        } else {
            #pragma unroll
            for (int s = 0; s < BK / 16; ++s) {
                const int kr = (t >> 4) + 16 * s;
                const int f4 = t & 15;
                float4 v = *(const float4*)(Bm + (long)(k0 + kr) * ldb + n0 + f4 * 4);
                *(float4*)(&Bs[kr][f4 * 4]) = v;
            }
        }
        __syncthreads();

        // --- compute: 4x4 microtile ---
        #pragma unroll
        for (int kk = 0; kk < BK; ++kk) {
            float4 a4 = *(const float4*)(&As[kk][ty * 4]);
            float4 b4 = *(const float4*)(&Bs[kk][tx * 4]);
            float av[4] = {a4.x, a4.y, a4.z, a4.w};
            float bv[4] = {b4.x, b4.y, b4.z, b4.w};
            #pragma unroll
            for (int i = 0; i < 4; ++i)
                #pragma unroll
                for (int j = 0; j < 4; ++j)
                    acc[i][j] += av[i] * bv[j];
        }
        __syncthreads();
    }

    // --- epilogue ---
    #pragma unroll
    for (int i = 0; i < 4; ++i) {
        const int m = m0 + ty * 4 + i;
        #pragma unroll
        for (int j = 0; j < 4; ++j) {
            const int n = n0 + tx * 4 + j;
            float v = acc[i][j] * scale + (bias ? bias[n] : 0.0f);
            if (OUTMODE == 1) {
                // token row m -> (b, s); feature col n -> (h, d)
                long off = ((long)((m / S_) * NH_ + n / HD_) * S_ + (m % S_)) * HD_ + (n % HD_);
                C[off] = v;
            } else if (OUTMODE == 2) {
                // z = b*NH + h; row m = q index; col n = d
                long off = (long)(z >> 3) * ((long)S_ * H_) + (long)(z & 7) * HD_
                         + (long)m * H_ + n;
                C[off] = v;
            } else {
                C[(long)m * ldc + n] = v;
            }
        }
    }
}

// ---------------------------------------------------------------------------
// Row softmax over attention logits: one CTA (256 threads) per 4096-wide row.
// Single pass: the row lives in registers (16 floats/thread).
// ---------------------------------------------------------------------------
__global__ void __launch_bounds__(256) softmax_k(float* __restrict__ attn)
{
    const long row = blockIdx.x;
    float4* p4 = (float4*)(attn + row * (long)S_);
    const int t = threadIdx.x;

    float4 v[4];
    float mx = -1e30f;
    #pragma unroll
    for (int s = 0; s < 4; ++s) {
        v[s] = p4[t + 256 * s];
        mx = fmaxf(mx, fmaxf(fmaxf(v[s].x, v[s].y), fmaxf(v[s].z, v[s].w)));
    }

    __shared__ float redmax[8];
    __shared__ float redsum[8];

    #pragma unroll
    for (int o = 16; o > 0; o >>= 1)
        mx = fmaxf(mx, __shfl_xor_sync(0xffffffffu, mx, o));
    if ((t & 31) == 0) redmax[t >> 5] = mx;
    __syncthreads();
    mx = redmax[0];
    #pragma unroll
    for (int w = 1; w < 8; ++w) mx = fmaxf(mx, redmax[w]);

    float sum = 0.0f;
    #pragma unroll
    for (int s = 0; s < 4; ++s) {
        v[s].x = __expf(v[s].x - mx);
        v[s].y = __expf(v[s].y - mx);
        v[s].z = __expf(v[s].z - mx);
        v[s].w = __expf(v[s].w - mx);
        sum += v[s].x + v[s].y + v[s].z + v[s].w;
    }
    #pragma unroll
    for (int o = 16; o > 0; o >>= 1)
        sum += __shfl_xor_sync(0xffffffffu, sum, o);
    if ((t & 31) == 0) redsum[t >> 5] = sum;
    __syncthreads();
    sum = 0.0f;
    #pragma unroll
    for (int w = 0; w < 8; ++w) sum += redsum[w];

    const float inv = 1.0f / sum;
    #pragma unroll
    for (int s = 0; s < 4; ++s) {
        v[s].x *= inv; v[s].y *= inv; v[s].z *= inv; v[s].w *= inv;
        p4[t + 256 * s] = v[s];
    }
}

// ---------------------------------------------------------------------------
// kernel_launch: graph-capturable, allocation-free pipeline.
// Inputs (metadata order): query, key, value, Wq, bq, Wk, bk, Wv, bv, Wo, bo
// Output layout assumption: [ x (B*S*H floats) | attention (B*NH*S*S floats) ]
// ---------------------------------------------------------------------------
extern "C" void kernel_launch(void* const* d_in, const int* in_sizes, int n_in,
                              void* d_out, int out_size)
{
    const float* query = (const float*)d_in[0];
    const float* key_  = (const float*)d_in[1];
    const float* value = (const float*)d_in[2];
    const float* Wq = (const float*)d_in[3];
    const float* bq = (const float*)d_in[4];
    const float* Wk = (const float*)d_in[5];
    const float* bk = (const float*)d_in[6];
    const float* Wv = (const float*)d_in[7];
    const float* bv = (const float*)d_in[8];
    const float* Wo = (const float*)d_in[9];
    const float* bo = (const float*)d_in[10];

    float* xout = (float*)d_out;

    float *Qp, *Kp, *Vp, *Cp, *Afb;
    cudaGetSymbolAddress((void**)&Qp, g_Q);
    cudaGetSymbolAddress((void**)&Kp, g_K);
    cudaGetSymbolAddress((void**)&Vp, g_V);
    cudaGetSymbolAddress((void**)&Cp, g_ctx);
    cudaGetSymbolAddress((void**)&Afb, g_attn_fb);

    // Attention matrix goes directly into d_out if it fits (tuple output),
    // otherwise into the device-global fallback.
    float* attn = ((long)out_size >= (long)XSZ + ASZ) ? (xout + XSZ) : Afb;

    const dim3 blk(256);
    const int M_TOK = B_ * S_;   // 8192

    // Q/K/V projections -> head-split scratch  (NT: x @ W^T + b)
    gemm_k<32, true, 1><<<dim3(H_ / 64, M_TOK / 64, 1), blk>>>(
        query, Wq, bq, Qp, M_TOK, H_, H_, H_, H_, 0, 0, 0, 0, 1.0f);
    gemm_k<32, true, 1><<<dim3(H_ / 64, M_TOK / 64, 1), blk>>>(
        key_, Wk, bk, Kp, M_TOK, H_, H_, H_, H_, 0, 0, 0, 0, 1.0f);
    gemm_k<32, true, 1><<<dim3(H_ / 64, M_TOK / 64, 1), blk>>>(
        value, Wv, bv, Vp, M_TOK, H_, H_, H_, H_, 0, 0, 0, 0, 1.0f);

    // energy = Q @ K^T / sqrt(HD), per (b,h)   (NT, K-dim = 64)
    gemm_k<64, true, 0><<<dim3(S_ / 64, S_ / 64, B_ * NH_), blk>>>(
        Qp, Kp, nullptr, attn, S_, S_, HD_, HD_, HD_, S_,
        (long)S_ * HD_, (long)S_ * HD_, (long)S_ * S_, 0.125f);

    // softmax rows (in place; attn now holds the attention output)
    softmax_k<<<B_ * NH_ * S_, 256>>>(attn);

    // ctx = attn @ V, per (b,h)   (NN), merged-head output [B,S,H]
    gemm_k<32, false, 2><<<dim3(1, S_ / 64, B_ * NH_), blk>>>(
        attn, Vp, nullptr, Cp, S_, HD_, S_, S_, HD_, 0,
        (long)S_ * S_, (long)S_ * HD_, 0, 1.0f);

    // x = ctx @ Wo^T + bo -> d_out  (NT)
    gemm_k<32, true, 0><<<dim3(H_ / 64, M_TOK / 64, 1), blk>>>(
        Cp, Wo, bo, xout, M_TOK, H_, H_, H_, H_, H_, 0, 0, 0, 1.0f);
}

// round 5
// speedup vs baseline: 1.1094x; 1.1094x over previous
#include <cuda_runtime.h>

// Problem constants
#define B_  2
#define S_  4096
#define H_  512
#define NH_ 8
#define HD_ 64
#define XSZ (B_ * S_ * H_)                       // 4,194,304 floats (x output)
#define ASZ ((long)B_ * NH_ * S_ * S_)           // 268,435,456 floats (attention)

// Scratch (device globals: the sanctioned allocation-free workaround)
__device__ float g_Q[B_ * NH_ * S_ * HD_];
__device__ float g_K[B_ * NH_ * S_ * HD_];
__device__ float g_V[B_ * NH_ * S_ * HD_];
__device__ float g_ctx[B_ * S_ * H_];
__device__ float g_attn_fb[(long)B_ * NH_ * S_ * S_];

// ---------------------------------------------------------------------------
// Tiled GEMM v2: C[M,N] = scale * (A x B) + bias
//   TM x TN tile, depth BK=32, 256 threads, 8x8 microtile per thread.
//   Requires TM*TN == 16384 (128x128 or 256x64).
//   A is [M,K] row-major. BNT ? B is [N,K] (NT) : B is [K,N] (NN).
//   Smem k-major, padded rows (+4 floats) -> 16B-aligned, conflict-free
//   LDS.128 in the compute loop.
//   OUTMODE 0: row-major C[m*ldc+n]; 1: head-split -> [B,NH,S,HD];
//   2: per-head (z=b*NH+h) result merged into [B,S,H].
// ---------------------------------------------------------------------------
template<int TM, int TN, bool BNT, int OUTMODE>
__global__ void __launch_bounds__(256, 2) gemm8(
    const float* __restrict__ A, const float* __restrict__ Bm,
    const float* __restrict__ bias, float* __restrict__ C,
    int K, int lda, int ldb, int ldc,
    long sAz, long sBz, long sCz, float scale)
{
    constexpr int BK  = 32;
    constexpr int PAD = 4;
    constexpr int CG  = TN / 8;              // column groups
    static_assert(TM * TN == 16384, "tile/thread mismatch");

    __shared__ __align__(16) float As[BK][TM + PAD];
    __shared__ __align__(16) float Bs[BK][TN + PAD];

    const int z = blockIdx.z;
    A  += (long)z * sAz;
    Bm += (long)z * sBz;
    C  += (long)z * sCz;

    const int m0 = blockIdx.y * TM;
    const int n0 = blockIdx.x * TN;
    const int t  = threadIdx.x;
    const int tx = t % CG;                    // col group
    const int ty = t / CG;                    // row group

    float acc[8][8] = {};

    for (int k0 = 0; k0 < K; k0 += BK) {
        // ---- load A tile, transpose to k-major ----
        constexpr int APT = (TM * BK / 4) / 256;   // float4 per thread
        #pragma unroll
        for (int s = 0; s < APT; ++s) {
            const int idx = t + 256 * s;
            const int r   = idx >> 3;              // BK/4 == 8
            const int c4  = idx & 7;
            float4 v = *(const float4*)(A + (long)(m0 + r) * lda + k0 + c4 * 4);
            As[c4*4 + 0][r] = v.x;
            As[c4*4 + 1][r] = v.y;
            As[c4*4 + 2][r] = v.z;
            As[c4*4 + 3][r] = v.w;
        }
        // ---- load B tile ----
        if (BNT) {
            constexpr int BPT = (TN * BK / 4) / 256;
            #pragma unroll
            for (int s = 0; s < BPT; ++s) {
                const int idx = t + 256 * s;
                const int r   = idx >> 3;
                const int c4  = idx & 7;
                float4 v = *(const float4*)(Bm + (long)(n0 + r) * ldb + k0 + c4 * 4);
                Bs[c4*4 + 0][r] = v.x;
                Bs[c4*4 + 1][r] = v.y;
                Bs[c4*4 + 2][r] = v.z;
                Bs[c4*4 + 3][r] = v.w;
            }
        } else {
            constexpr int BPT = (BK * TN / 4) / 256;
            #pragma unroll
            for (int s = 0; s < BPT; ++s) {
                const int idx = t + 256 * s;
                const int kr  = idx / (TN / 4);
                const int c4  = idx % (TN / 4);
                float4 v = *(const float4*)(Bm + (long)(k0 + kr) * ldb + n0 + c4 * 4);
                *(float4*)(&Bs[kr][c4 * 4]) = v;
            }
        }
        __syncthreads();

        // ---- compute: 8x8 microtile ----
        #pragma unroll
        for (int kk = 0; kk < BK; ++kk) {
            float a[8], b[8];
            *(float4*)(a)     = *(const float4*)(&As[kk][ty * 8]);
            *(float4*)(a + 4) = *(const float4*)(&As[kk][ty * 8 + 4]);
            *(float4*)(b)     = *(const float4*)(&Bs[kk][tx * 8]);
            *(float4*)(b + 4) = *(const float4*)(&Bs[kk][tx * 8 + 4]);
            #pragma unroll
            for (int i = 0; i < 8; ++i)
                #pragma unroll
                for (int j = 0; j < 8; ++j)
                    acc[i][j] += a[i] * b[j];
        }
        __syncthreads();
    }

    // ---- epilogue (vectorized float4 stores) ----
    const int nb = n0 + tx * 8;
    float bz[8];
    #pragma unroll
    for (int j = 0; j < 8; ++j) bz[j] = bias ? bias[nb + j] : 0.0f;

    #pragma unroll
    for (int i = 0; i < 8; ++i) {
        const int m = m0 + ty * 8 + i;
        float v[8];
        #pragma unroll
        for (int j = 0; j < 8; ++j) v[j] = acc[i][j] * scale + bz[j];

        float* dst;
        if (OUTMODE == 1) {
            // token row m -> (b,s); feature col nb -> (h,d); 8 cols same head (8|64)
            const int bb = m / S_, ss = m % S_;
            const int hh = nb / HD_, dd = nb % HD_;
            dst = C + (((long)(bb * NH_ + hh) * S_ + ss) * HD_ + dd);
        } else if (OUTMODE == 2) {
            // z = b*NH+h; row m = q; col nb = d (n0==0 here)
            dst = C + ((long)(z >> 3) * ((long)S_ * H_) + (long)(z & 7) * HD_
                      + (long)m * H_ + nb);
        } else {
            dst = C + ((long)m * ldc + nb);
        }
        *(float4*)(dst)     = make_float4(v[0], v[1], v[2], v[3]);
        *(float4*)(dst + 4) = make_float4(v[4], v[5], v[6], v[7]);
    }
}

// ---------------------------------------------------------------------------
// Row softmax: one CTA (256 threads) per 4096-wide row, row in registers.
// ---------------------------------------------------------------------------
__global__ void __launch_bounds__(256) softmax_k(float* __restrict__ attn)
{
    const long row = blockIdx.x;
    float4* p4 = (float4*)(attn + row * (long)S_);
    const int t = threadIdx.x;

    float4 v[4];
    float mx = -1e30f;
    #pragma unroll
    for (int s = 0; s < 4; ++s) {
        v[s] = p4[t + 256 * s];
        mx = fmaxf(mx, fmaxf(fmaxf(v[s].x, v[s].y), fmaxf(v[s].z, v[s].w)));
    }

    __shared__ float redmax[8];
    __shared__ float redsum[8];

    #pragma unroll
    for (int o = 16; o > 0; o >>= 1)
        mx = fmaxf(mx, __shfl_xor_sync(0xffffffffu, mx, o));
    if ((t & 31) == 0) redmax[t >> 5] = mx;
    __syncthreads();
    mx = redmax[0];
    #pragma unroll
    for (int w = 1; w < 8; ++w) mx = fmaxf(mx, redmax[w]);

    float sum = 0.0f;
    #pragma unroll
    for (int s = 0; s < 4; ++s) {
        v[s].x = __expf(v[s].x - mx);
        v[s].y = __expf(v[s].y - mx);
        v[s].z = __expf(v[s].z - mx);
        v[s].w = __expf(v[s].w - mx);
        sum += v[s].x + v[s].y + v[s].z + v[s].w;
    }
    #pragma unroll
    for (int o = 16; o > 0; o >>= 1)
        sum += __shfl_xor_sync(0xffffffffu, sum, o);
    if ((t & 31) == 0) redsum[t >> 5] = sum;
    __syncthreads();
    sum = 0.0f;
    #pragma unroll
    for (int w = 0; w < 8; ++w) sum += redsum[w];

    const float inv = 1.0f / sum;
    #pragma unroll
    for (int s = 0; s < 4; ++s) {
        v[s].x *= inv; v[s].y *= inv; v[s].z *= inv; v[s].w *= inv;
        p4[t + 256 * s] = v[s];
    }
}

// ---------------------------------------------------------------------------
// kernel_launch
// Inputs: query, key, value, Wq, bq, Wk, bk, Wv, bv, Wo, bo
// Output: [ x (B*S*H) | attention (B*NH*S*S) ]
// ---------------------------------------------------------------------------
extern "C" void kernel_launch(void* const* d_in, const int* in_sizes, int n_in,
                              void* d_out, int out_size)
{
    const float* query = (const float*)d_in[0];
    const float* key_  = (const float*)d_in[1];
    const float* value = (const float*)d_in[2];
    const float* Wq = (const float*)d_in[3];
    const float* bq = (const float*)d_in[4];
    const float* Wk = (const float*)d_in[5];
    const float* bk = (const float*)d_in[6];
    const float* Wv = (const float*)d_in[7];
    const float* bv = (const float*)d_in[8];
    const float* Wo = (const float*)d_in[9];
    const float* bo = (const float*)d_in[10];

    float* xout = (float*)d_out;

    float *Qp, *Kp, *Vp, *Cp, *Afb;
    cudaGetSymbolAddress((void**)&Qp, g_Q);
    cudaGetSymbolAddress((void**)&Kp, g_K);
    cudaGetSymbolAddress((void**)&Vp, g_V);
    cudaGetSymbolAddress((void**)&Cp, g_ctx);
    cudaGetSymbolAddress((void**)&Afb, g_attn_fb);

    float* attn = ((long)out_size >= (long)XSZ + ASZ) ? (xout + XSZ) : Afb;

    const dim3 blk(256);

    // Q/K/V projections -> head-split scratch (NT), 128x128 tiles
    gemm8<128, 128, true, 1><<<dim3(H_ / 128, (B_ * S_) / 128, 1), blk>>>(
        query, Wq, bq, Qp, H_, H_, H_, 0, 0, 0, 0, 1.0f);
    gemm8<128, 128, true, 1><<<dim3(H_ / 128, (B_ * S_) / 128, 1), blk>>>(
        key_, Wk, bk, Kp, H_, H_, H_, 0, 0, 0, 0, 1.0f);
    gemm8<128, 128, true, 1><<<dim3(H_ / 128, (B_ * S_) / 128, 1), blk>>>(
        value, Wv, bv, Vp, H_, H_, H_, 0, 0, 0, 0, 1.0f);

    // energy = Q @ K^T / 8, per (b,h) (NT, K=64), 128x128 tiles
    gemm8<128, 128, true, 0><<<dim3(S_ / 128, S_ / 128, B_ * NH_), blk>>>(
        Qp, Kp, nullptr, attn, HD_, HD_, HD_, S_,
        (long)S_ * HD_, (long)S_ * HD_, (long)S_ * S_, 0.125f);

    // softmax rows (in place)
    softmax_k<<<B_ * NH_ * S_, 256>>>(attn);

    // ctx = attn @ V, per (b,h) (NN), 256x64 tiles, merged-head output
    gemm8<256, 64, false, 2><<<dim3(1, S_ / 256, B_ * NH_), blk>>>(
        attn, Vp, nullptr, Cp, S_, S_, HD_, 0,
        (long)S_ * S_, (long)S_ * HD_, 0, 1.0f);

    // x = ctx @ Wo^T + bo -> d_out (NT)
    gemm8<128, 128, true, 0><<<dim3(H_ / 128, (B_ * S_) / 128, 1), blk>>>(
        Cp, Wo, bo, xout, H_, H_, H_, H_, 0, 0, 0, 1.0f);
}

// round 6
// speedup vs baseline: 1.9398x; 1.7486x over previous
#include <cuda_runtime.h>

// Problem constants
#define B_  2
#define S_  4096
#define H_  512
#define NH_ 8
#define HD_ 64
#define XSZ (B_ * S_ * H_)                       // 4,194,304 floats (x output)
#define ASZ ((long)B_ * NH_ * S_ * S_)           // 268,435,456 floats (attention)

// Scratch (device globals: the sanctioned allocation-free workaround)
__device__ float g_Q[B_ * NH_ * S_ * HD_];
__device__ float g_K[B_ * NH_ * S_ * HD_];
__device__ float g_V[B_ * NH_ * S_ * HD_];
__device__ float g_ctx[B_ * S_ * H_];
__device__ float g_attn_fb[(long)B_ * NH_ * S_ * S_];

// ---- tf32 helpers -----------------------------------------------------------
__device__ __forceinline__ float f2tf32(float f) {
    unsigned u;
    asm("cvt.rna.tf32.f32 %0, %1;" : "=r"(u) : "f"(f));
    return __uint_as_float(u);
}

__device__ __forceinline__ void mma_tf32(float* c, const unsigned* a, const unsigned* b) {
    asm volatile(
        "mma.sync.aligned.m16n8k8.row.col.f32.tf32.tf32.f32 "
        "{%0,%1,%2,%3}, {%4,%5,%6,%7}, {%8,%9}, {%0,%1,%2,%3};"
        : "+f"(c[0]), "+f"(c[1]), "+f"(c[2]), "+f"(c[3])
        : "r"(a[0]), "r"(a[1]), "r"(a[2]), "r"(a[3]), "r"(b[0]), "r"(b[1]));
}

// ---------------------------------------------------------------------------
// tf32 tensor-core GEMM: C[M,N] = scale * (A x B) + bias
//   Block tile TM x TN, BK = 32, 256 threads (8 warps), warp tile WM x WN,
//   mma.sync m16n8k8 (row.col), fp32 accumulate.
//   A is [M,K] row-major. BNT ? B is [N,K] (NT) : B is [K,N] (NN).
//   Smem: As[m][k], Bs[n][k], row stride 36 floats (= 4 mod 32 banks ->
//   conflict-free fragment gather; 144B rows keep float4 fills aligned).
//   OUTMODE 0: row-major C[m*ldc+n]; 1: head-split -> [B,NH,S,HD];
//   2: per-head (z=b*NH+h) result merged into [B,S,H].
// ---------------------------------------------------------------------------
template<int TM, int TN, int WM, int WN, bool BNT, int OUTMODE>
__global__ void __launch_bounds__(256) gemm_tc(
    const float* __restrict__ A, const float* __restrict__ Bm,
    const float* __restrict__ bias, float* __restrict__ C,
    int K, int lda, int ldb, int ldc,
    long sAz, long sBz, long sCz, float scale)
{
    constexpr int BK  = 32;
    constexpr int LDS = BK + 4;              // 36 floats
    constexpr int WGN = TN / WN;             // warps along N
    constexpr int MT  = WM / 16;             // m16 tiles per warp
    constexpr int NT  = WN / 8;              // n8 tiles per warp
    static_assert((TM / WM) * WGN == 8, "warp grid must be 8 warps");

    __shared__ __align__(16) float As[TM][LDS];
    __shared__ __align__(16) float Bs[TN][LDS];

    const int z = blockIdx.z;
    A  += (long)z * sAz;
    Bm += (long)z * sBz;
    C  += (long)z * sCz;

    const int m0 = blockIdx.y * TM;
    const int n0 = blockIdx.x * TN;
    const int t    = threadIdx.x;
    const int warp = t >> 5;
    const int lane = t & 31;
    const int wm = warp / WGN;               // warp row
    const int wn = warp % WGN;               // warp col
    const int lr = lane >> 2;                // lane row (0..7)
    const int lc = lane & 3;                 // lane col (0..3)

    float acc[MT][NT][4] = {};

    for (int k0 = 0; k0 < K; k0 += BK) {
        // ---- fill A tile: [m][k], tf32-converted ----
        #pragma unroll
        for (int s = 0; s < TM / 32; ++s) {      // (TM*BK/4)/256
            const int idx = t + 256 * s;
            const int r   = idx >> 3;            // BK/4 == 8 float4 per row
            const int c4  = idx & 7;
            float4 v = *(const float4*)(A + (long)(m0 + r) * lda + k0 + c4 * 4);
            *(float4*)(&As[r][c4 * 4]) =
                make_float4(f2tf32(v.x), f2tf32(v.y), f2tf32(v.z), f2tf32(v.w));
        }
        // ---- fill B tile: [n][k] ----
        if (BNT) {
            #pragma unroll
            for (int s = 0; s < TN / 32; ++s) {
                const int idx = t + 256 * s;
                const int r   = idx >> 3;
                const int c4  = idx & 7;
                float4 v = *(const float4*)(Bm + (long)(n0 + r) * ldb + k0 + c4 * 4);
                *(float4*)(&Bs[r][c4 * 4]) =
                    make_float4(f2tf32(v.x), f2tf32(v.y), f2tf32(v.z), f2tf32(v.w));
            }
        } else {
            #pragma unroll
            for (int s = 0; s < (BK * TN / 4) / 256; ++s) {
                const int idx = t + 256 * s;
                const int kr  = idx / (TN / 4);
                const int c4  = idx % (TN / 4);
                float4 v = *(const float4*)(Bm + (long)(k0 + kr) * ldb + n0 + c4 * 4);
                Bs[c4 * 4 + 0][kr] = f2tf32(v.x);
                Bs[c4 * 4 + 1][kr] = f2tf32(v.y);
                Bs[c4 * 4 + 2][kr] = f2tf32(v.z);
                Bs[c4 * 4 + 3][kr] = f2tf32(v.w);
            }
        }
        __syncthreads();

        // ---- compute: BK/8 k-steps of m16n8k8 ----
        #pragma unroll
        for (int ks = 0; ks < BK / 8; ++ks) {
            const int kc = ks * 8 + lc;
            unsigned a[MT][4], b[NT][2];
            #pragma unroll
            for (int i = 0; i < MT; ++i) {
                const int row = wm * WM + i * 16 + lr;
                a[i][0] = __float_as_uint(As[row    ][kc    ]);
                a[i][1] = __float_as_uint(As[row + 8][kc    ]);
                a[i][2] = __float_as_uint(As[row    ][kc + 4]);
                a[i][3] = __float_as_uint(As[row + 8][kc + 4]);
            }
            #pragma unroll
            for (int j = 0; j < NT; ++j) {
                const int col = wn * WN + j * 8 + lr;
                b[j][0] = __float_as_uint(Bs[col][kc    ]);
                b[j][1] = __float_as_uint(Bs[col][kc + 4]);
            }
            #pragma unroll
            for (int i = 0; i < MT; ++i)
                #pragma unroll
                for (int j = 0; j < NT; ++j)
                    mma_tf32(acc[i][j], a[i], b[j]);
        }
        __syncthreads();
    }

    // ---- epilogue: scale + bias, float2 stores ----
    #pragma unroll
    for (int i = 0; i < MT; ++i) {
        #pragma unroll
        for (int j = 0; j < NT; ++j) {
            const int rr = m0 + wm * WM + i * 16 + lr;
            const int cc = n0 + wn * WN + j * 8 + 2 * lc;
            float b0 = bias ? bias[cc] : 0.0f;
            float b1 = bias ? bias[cc + 1] : 0.0f;
            float2 v0 = make_float2(acc[i][j][0] * scale + b0,
                                    acc[i][j][1] * scale + b1);
            float2 v1 = make_float2(acc[i][j][2] * scale + b0,
                                    acc[i][j][3] * scale + b1);
            #pragma unroll
            for (int h = 0; h < 2; ++h) {
                const int m = rr + h * 8;
                const float2 v = h ? v1 : v0;
                float* dst;
                if (OUTMODE == 1) {
                    const int bb = m / S_, ss = m % S_;
                    const int hh = cc / HD_, dd = cc % HD_;
                    dst = C + (((long)(bb * NH_ + hh) * S_ + ss) * HD_ + dd);
                } else if (OUTMODE == 2) {
                    dst = C + ((long)(z >> 3) * ((long)S_ * H_)
                              + (long)(z & 7) * HD_ + (long)m * H_ + cc);
                } else {
                    dst = C + ((long)m * ldc + cc);
                }
                *(float2*)dst = v;
            }
        }
    }
}

// ---------------------------------------------------------------------------
// Row softmax: one CTA (256 threads) per 4096-wide row, row in registers.
// Already at ~HBM roofline; unchanged.
// ---------------------------------------------------------------------------
__global__ void __launch_bounds__(256) softmax_k(float* __restrict__ attn)
{
    const long row = blockIdx.x;
    float4* p4 = (float4*)(attn + row * (long)S_);
    const int t = threadIdx.x;

    float4 v[4];
    float mx = -1e30f;
    #pragma unroll
    for (int s = 0; s < 4; ++s) {
        v[s] = p4[t + 256 * s];
        mx = fmaxf(mx, fmaxf(fmaxf(v[s].x, v[s].y), fmaxf(v[s].z, v[s].w)));
    }

    __shared__ float redmax[8];
    __shared__ float redsum[8];

    #pragma unroll
    for (int o = 16; o > 0; o >>= 1)
        mx = fmaxf(mx, __shfl_xor_sync(0xffffffffu, mx, o));
    if ((t & 31) == 0) redmax[t >> 5] = mx;
    __syncthreads();
    mx = redmax[0];
    #pragma unroll
    for (int w = 1; w < 8; ++w) mx = fmaxf(mx, redmax[w]);

    float sum = 0.0f;
    #pragma unroll
    for (int s = 0; s < 4; ++s) {
        v[s].x = __expf(v[s].x - mx);
        v[s].y = __expf(v[s].y - mx);
        v[s].z = __expf(v[s].z - mx);
        v[s].w = __expf(v[s].w - mx);
        sum += v[s].x + v[s].y + v[s].z + v[s].w;
    }
    #pragma unroll
    for (int o = 16; o > 0; o >>= 1)
        sum += __shfl_xor_sync(0xffffffffu, sum, o);
    if ((t & 31) == 0) redsum[t >> 5] = sum;
    __syncthreads();
    sum = 0.0f;
    #pragma unroll
    for (int w = 0; w < 8; ++w) sum += redsum[w];

    const float inv = 1.0f / sum;
    #pragma unroll
    for (int s = 0; s < 4; ++s) {
        v[s].x *= inv; v[s].y *= inv; v[s].z *= inv; v[s].w *= inv;
        p4[t + 256 * s] = v[s];
    }
}

// ---------------------------------------------------------------------------
// kernel_launch
// Inputs: query, key, value, Wq, bq, Wk, bk, Wv, bv, Wo, bo
// Output: [ x (B*S*H) | attention (B*NH*S*S) ]
// ---------------------------------------------------------------------------
extern "C" void kernel_launch(void* const* d_in, const int* in_sizes, int n_in,
                              void* d_out, int out_size)
{
    const float* query = (const float*)d_in[0];
    const float* key_  = (const float*)d_in[1];
    const float* value = (const float*)d_in[2];
    const float* Wq = (const float*)d_in[3];
    const float* bq = (const float*)d_in[4];
    const float* Wk = (const float*)d_in[5];
    const float* bk = (const float*)d_in[6];
    const float* Wv = (const float*)d_in[7];
    const float* bv = (const float*)d_in[8];
    const float* Wo = (const float*)d_in[9];
    const float* bo = (const float*)d_in[10];

    float* xout = (float*)d_out;

    float *Qp, *Kp, *Vp, *Cp, *Afb;
    cudaGetSymbolAddress((void**)&Qp, g_Q);
    cudaGetSymbolAddress((void**)&Kp, g_K);
    cudaGetSymbolAddress((void**)&Vp, g_V);
    cudaGetSymbolAddress((void**)&Cp, g_ctx);
    cudaGetSymbolAddress((void**)&Afb, g_attn_fb);

    float* attn = ((long)out_size >= (long)XSZ + ASZ) ? (xout + XSZ) : Afb;

    const dim3 blk(256);

    // Q/K/V projections -> head-split scratch (NT), tf32 tensor cores
    gemm_tc<128, 128, 32, 64, true, 1><<<dim3(H_ / 128, (B_ * S_) / 128, 1), blk>>>(
        query, Wq, bq, Qp, H_, H_, H_, 0, 0, 0, 0, 1.0f);
    gemm_tc<128, 128, 32, 64, true, 1><<<dim3(H_ / 128, (B_ * S_) / 128, 1), blk>>>(
        key_, Wk, bk, Kp, H_, H_, H_, 0, 0, 0, 0, 1.0f);
    gemm_tc<128, 128, 32, 64, true, 1><<<dim3(H_ / 128, (B_ * S_) / 128, 1), blk>>>(
        value, Wv, bv, Vp, H_, H_, H_, 0, 0, 0, 0, 1.0f);

    // energy = Q @ K^T / 8, per (b,h) (NT, K=64)
    gemm_tc<128, 128, 32, 64, true, 0><<<dim3(S_ / 128, S_ / 128, B_ * NH_), blk>>>(
        Qp, Kp, nullptr, attn, HD_, HD_, HD_, S_,
        (long)S_ * HD_, (long)S_ * HD_, (long)S_ * S_, 0.125f);

    // softmax rows (in place)
    softmax_k<<<B_ * NH_ * S_, 256>>>(attn);

    // ctx = attn @ V, per (b,h) (NN), merged-head output [B,S,H]
    gemm_tc<128, 64, 32, 32, false, 2><<<dim3(1, S_ / 128, B_ * NH_), blk>>>(
        attn, Vp, nullptr, Cp, S_, S_, HD_, 0,
        (long)S_ * S_, (long)S_ * HD_, 0, 1.0f);

    // x = ctx @ Wo^T + bo -> d_out (NT)
    gemm_tc<128, 128, 32, 64, true, 0><<<dim3(H_ / 128, (B_ * S_) / 128, 1), blk>>>(
        Cp, Wo, bo, xout, H_, H_, H_, H_, 0, 0, 0, 1.0f);
}

// round 7
// speedup vs baseline: 2.0977x; 1.0814x over previous
#include <cuda_runtime.h>

// Problem constants
#define B_  2
#define S_  4096
#define H_  512
#define NH_ 8
#define HD_ 64
#define XSZ (B_ * S_ * H_)                       // 4,194,304 floats (x output)
#define ASZ ((long)B_ * NH_ * S_ * S_)           // 268,435,456 floats (attention)
#define GXE (S_ / 128)                           // energy col-tiles per row = 32

// Scratch (device globals: the sanctioned allocation-free workaround)
__device__ float g_Q[B_ * NH_ * S_ * HD_];
__device__ float g_K[B_ * NH_ * S_ * HD_];
__device__ float g_V[B_ * NH_ * S_ * HD_];
__device__ float g_ctx[B_ * S_ * H_];
__device__ float g_psum[(long)B_ * NH_ * S_ * GXE];   // per-row exp partial sums
__device__ float g_attn_fb[(long)B_ * NH_ * S_ * S_]; // fallback if d_out lacks attention

// ---- tf32 helpers -----------------------------------------------------------
__device__ __forceinline__ float f2tf32(float f) {
    unsigned u;
    asm("cvt.rna.tf32.f32 %0, %1;" : "=r"(u) : "f"(f));
    return __uint_as_float(u);
}

__device__ __forceinline__ void mma_tf32(float* c, const unsigned* a, const unsigned* b) {
    asm volatile(
        "mma.sync.aligned.m16n8k8.row.col.f32.tf32.tf32.f32 "
        "{%0,%1,%2,%3}, {%4,%5,%6,%7}, {%8,%9}, {%0,%1,%2,%3};"
        : "+f"(c[0]), "+f"(c[1]), "+f"(c[2]), "+f"(c[3])
        : "r"(a[0]), "r"(a[1]), "r"(a[2]), "r"(a[3]), "r"(b[0]), "r"(b[1]));
}

// ---------------------------------------------------------------------------
// tf32 tensor-core GEMM: C[M,N] = scale * (A x B) + bias
//   Block tile TM x TN, BK = 32, 256 threads (8 warps), warp tile WM x WN,
//   mma.sync m16n8k8 (row.col), fp32 accumulate.
//   A is [M,K] row-major. BNT ? B is [N,K] (NT) : B is [K,N] (NN).
//   Smem: As[m][k], Bs[n][k], row stride 36 floats (conflict-free gather).
//   OUTMODE 0: row-major C[m*ldc+n]; 1: head-split -> [B,NH,S,HD];
//   2: per-head (z=b*NH+h) result merged into [B,S,H].
//   SOFT: epilogue writes exp(scale*acc) (unnormalized softmax numerator)
//         and per-row partial sums to psum[(z*S + row)*GXE + blockIdx.x].
//   NORM: A is an unnormalized exp matrix; prologue builds 1/rowsum from
//         psum; A-tiles are normalized on load and written back (fp32) via Aw.
// ---------------------------------------------------------------------------
template<int TM, int TN, int WM, int WN, bool BNT, int OUTMODE, bool SOFT, bool NORM>
__global__ void __launch_bounds__(256) gemm_tc(
    const float* __restrict__ A, const float* __restrict__ Bm,
    const float* __restrict__ bias, float* __restrict__ C,
    float* __restrict__ psum, float* __restrict__ Aw,
    int K, int lda, int ldb, int ldc,
    long sAz, long sBz, long sCz, float scale)
{
    constexpr int BK  = 32;
    constexpr int LDS = BK + 4;              // 36 floats
    constexpr int WGN = TN / WN;             // warps along N
    constexpr int MT  = WM / 16;             // m16 tiles per warp
    constexpr int NT  = WN / 8;              // n8 tiles per warp
    static_assert((TM / WM) * WGN == 8, "warp grid must be 8 warps");
    static_assert(!SOFT || WGN == 2, "SOFT epilogue assumes 2 warp columns");

    __shared__ __align__(16) float As[TM][LDS];
    __shared__ __align__(16) float Bs[TN][LDS];
    __shared__ float rsum[SOFT ? TM : 1][2];
    __shared__ float inv_s[NORM ? TM : 1];

    const int z = blockIdx.z;
    A  += (long)z * sAz;
    Bm += (long)z * sBz;
    C  += (long)z * sCz;
    if (NORM) Aw += (long)z * sAz;

    const int m0 = blockIdx.y * TM;
    const int n0 = blockIdx.x * TN;
    const int t    = threadIdx.x;
    const int warp = t >> 5;
    const int lane = t & 31;
    const int wm = warp / WGN;               // warp row
    const int wn = warp % WGN;               // warp col
    const int lr = lane >> 2;                // lane row (0..7)
    const int lc = lane & 3;                 // lane col (0..3)

    // ---- NORM prologue: 1/rowsum from psum partials ----
    if (NORM) {
        if (t < TM) {
            const float4* pp = (const float4*)(psum + ((long)z * S_ + m0 + t) * GXE);
            float s = 0.0f;
            #pragma unroll
            for (int q = 0; q < GXE / 4; ++q) {
                float4 v = pp[q];
                s += (v.x + v.y) + (v.z + v.w);
            }
            inv_s[t] = 1.0f / s;
        }
        __syncthreads();
    }

    float acc[MT][NT][4] = {};

    for (int k0 = 0; k0 < K; k0 += BK) {
        // ---- fill A tile: [m][k], tf32-converted ----
        #pragma unroll
        for (int s = 0; s < TM / 32; ++s) {      // (TM*BK/4)/256
            const int idx = t + 256 * s;
            const int r   = idx >> 3;            // 8 float4 per row
            const int c4  = idx & 7;
            float4 v = *(const float4*)(A + (long)(m0 + r) * lda + k0 + c4 * 4);
            if (NORM) {
                const float iv = inv_s[r];
                v.x *= iv; v.y *= iv; v.z *= iv; v.w *= iv;
                *(float4*)(Aw + (long)(m0 + r) * lda + k0 + c4 * 4) = v;  // final attn
            }
            *(float4*)(&As[r][c4 * 4]) =
                make_float4(f2tf32(v.x), f2tf32(v.y), f2tf32(v.z), f2tf32(v.w));
        }
        // ---- fill B tile: [n][k] ----
        if (BNT) {
            #pragma unroll
            for (int s = 0; s < TN / 32; ++s) {
                const int idx = t + 256 * s;
                const int r   = idx >> 3;
                const int c4  = idx & 7;
                float4 v = *(const float4*)(Bm + (long)(n0 + r) * ldb + k0 + c4 * 4);
                *(float4*)(&Bs[r][c4 * 4]) =
                    make_float4(f2tf32(v.x), f2tf32(v.y), f2tf32(v.z), f2tf32(v.w));
            }
        } else {
            #pragma unroll
            for (int s = 0; s < (BK * TN / 4) / 256; ++s) {
                const int idx = t + 256 * s;
                const int kr  = idx / (TN / 4);
                const int c4  = idx % (TN / 4);
                float4 v = *(const float4*)(Bm + (long)(k0 + kr) * ldb + n0 + c4 * 4);
                Bs[c4 * 4 + 0][kr] = f2tf32(v.x);
                Bs[c4 * 4 + 1][kr] = f2tf32(v.y);
                Bs[c4 * 4 + 2][kr] = f2tf32(v.z);
                Bs[c4 * 4 + 3][kr] = f2tf32(v.w);
            }
        }
        __syncthreads();

        // ---- compute: BK/8 k-steps of m16n8k8 ----
        #pragma unroll
        for (int ks = 0; ks < BK / 8; ++ks) {
            const int kc = ks * 8 + lc;
            unsigned a[MT][4], b[NT][2];
            #pragma unroll
            for (int i = 0; i < MT; ++i) {
                const int row = wm * WM + i * 16 + lr;
                a[i][0] = __float_as_uint(As[row    ][kc    ]);
                a[i][1] = __float_as_uint(As[row + 8][kc    ]);
                a[i][2] = __float_as_uint(As[row    ][kc + 4]);
                a[i][3] = __float_as_uint(As[row + 8][kc + 4]);
            }
            #pragma unroll
            for (int j = 0; j < NT; ++j) {
                const int col = wn * WN + j * 8 + lr;
                b[j][0] = __float_as_uint(Bs[col][kc    ]);
                b[j][1] = __float_as_uint(Bs[col][kc + 4]);
            }
            #pragma unroll
            for (int i = 0; i < MT; ++i)
                #pragma unroll
                for (int j = 0; j < NT; ++j)
                    mma_tf32(acc[i][j], a[i], b[j]);
        }
        __syncthreads();
    }

    // ---- SOFT epilogue: exp + partial row sums ----
    if (SOFT) {
        #pragma unroll
        for (int i = 0; i < MT; ++i) {
            const int rr = m0 + wm * WM + i * 16 + lr;
            float s0 = 0.0f, s1 = 0.0f;
            #pragma unroll
            for (int j = 0; j < NT; ++j) {
                const int cc = n0 + wn * WN + j * 8 + 2 * lc;
                float e0 = __expf(acc[i][j][0] * scale);
                float e1 = __expf(acc[i][j][1] * scale);
                float e2 = __expf(acc[i][j][2] * scale);
                float e3 = __expf(acc[i][j][3] * scale);
                s0 += e0 + e1;
                s1 += e2 + e3;
                *(float2*)(C + (long)rr * ldc + cc)       = make_float2(e0, e1);
                *(float2*)(C + (long)(rr + 8) * ldc + cc) = make_float2(e2, e3);
            }
            // reduce over the 4 lanes (lc) sharing each row
            s0 += __shfl_xor_sync(0xffffffffu, s0, 1);
            s0 += __shfl_xor_sync(0xffffffffu, s0, 2);
            s1 += __shfl_xor_sync(0xffffffffu, s1, 1);
            s1 += __shfl_xor_sync(0xffffffffu, s1, 2);
            if (lc == 0) {
                rsum[wm * WM + i * 16 + lr    ][wn] = s0;
                rsum[wm * WM + i * 16 + 8 + lr][wn] = s1;
            }
        }
        __syncthreads();
        if (t < TM)
            psum[((long)z * S_ + m0 + t) * GXE + blockIdx.x] = rsum[t][0] + rsum[t][1];
        return;
    }

    // ---- standard epilogue: scale + bias, float2 stores ----
    #pragma unroll
    for (int i = 0; i < MT; ++i) {
        #pragma unroll
        for (int j = 0; j < NT; ++j) {
            const int rr = m0 + wm * WM + i * 16 + lr;
            const int cc = n0 + wn * WN + j * 8 + 2 * lc;
            float b0 = bias ? bias[cc] : 0.0f;
            float b1 = bias ? bias[cc + 1] : 0.0f;
            float2 v0 = make_float2(acc[i][j][0] * scale + b0,
                                    acc[i][j][1] * scale + b1);
            float2 v1 = make_float2(acc[i][j][2] * scale + b0,
                                    acc[i][j][3] * scale + b1);
            #pragma unroll
            for (int h = 0; h < 2; ++h) {
                const int m = rr + h * 8;
                const float2 v = h ? v1 : v0;
                float* dst;
                if (OUTMODE == 1) {
                    const int bb = m / S_, ss = m % S_;
                    const int hh = cc / HD_, dd = cc % HD_;
                    dst = C + (((long)(bb * NH_ + hh) * S_ + ss) * HD_ + dd);
                } else if (OUTMODE == 2) {
                    dst = C + ((long)(z >> 3) * ((long)S_ * H_)
                              + (long)(z & 7) * HD_ + (long)m * H_ + cc);
                } else {
                    dst = C + ((long)m * ldc + cc);
                }
                *(float2*)dst = v;
            }
        }
    }
}

// ---------------------------------------------------------------------------
// kernel_launch
// Inputs: query, key, value, Wq, bq, Wk, bk, Wv, bv, Wo, bo
// Output: [ x (B*S*H) | attention (B*NH*S*S) ]
// ---------------------------------------------------------------------------
extern "C" void kernel_launch(void* const* d_in, const int* in_sizes, int n_in,
                              void* d_out, int out_size)
{
    const float* query = (const float*)d_in[0];
    const float* key_  = (const float*)d_in[1];
    const float* value = (const float*)d_in[2];
    const float* Wq = (const float*)d_in[3];
    const float* bq = (const float*)d_in[4];
    const float* Wk = (const float*)d_in[5];
    const float* bk = (const float*)d_in[6];
    const float* Wv = (const float*)d_in[7];
    const float* bv = (const float*)d_in[8];
    const float* Wo = (const float*)d_in[9];
    const float* bo = (const float*)d_in[10];

    float* xout = (float*)d_out;

    float *Qp, *Kp, *Vp, *Cp, *Pp, *Afb;
    cudaGetSymbolAddress((void**)&Qp, g_Q);
    cudaGetSymbolAddress((void**)&Kp, g_K);
    cudaGetSymbolAddress((void**)&Vp, g_V);
    cudaGetSymbolAddress((void**)&Cp, g_ctx);
    cudaGetSymbolAddress((void**)&Pp, g_psum);
    cudaGetSymbolAddress((void**)&Afb, g_attn_fb);

    float* attn = ((long)out_size >= (long)XSZ + ASZ) ? (xout + XSZ) : Afb;

    const dim3 blk(256);

    // Q/K/V projections -> head-split scratch (NT), tf32 tensor cores
    gemm_tc<128, 128, 32, 64, true, 1, false, false>
        <<<dim3(H_ / 128, (B_ * S_) / 128, 1), blk>>>(
        query, Wq, bq, Qp, nullptr, nullptr, H_, H_, H_, 0, 0, 0, 0, 1.0f);
    gemm_tc<128, 128, 32, 64, true, 1, false, false>
        <<<dim3(H_ / 128, (B_ * S_) / 128, 1), blk>>>(
        key_, Wk, bk, Kp, nullptr, nullptr, H_, H_, H_, 0, 0, 0, 0, 1.0f);
    gemm_tc<128, 128, 32, 64, true, 1, false, false>
        <<<dim3(H_ / 128, (B_ * S_) / 128, 1), blk>>>(
        value, Wv, bv, Vp, nullptr, nullptr, H_, H_, H_, 0, 0, 0, 0, 1.0f);

    // energy+exp: attn = exp(Q @ K^T / 8) (unnormalized), psum = row partials
    gemm_tc<128, 128, 32, 64, true, 0, true, false>
        <<<dim3(S_ / 128, S_ / 128, B_ * NH_), blk>>>(
        Qp, Kp, nullptr, attn, Pp, nullptr, HD_, HD_, HD_, S_,
        (long)S_ * HD_, (long)S_ * HD_, (long)S_ * S_, 0.125f);

    // ctx = softmax(attn) @ V: normalizes attn tiles on load, writes the
    // normalized attention back in place (final output), MMA per (b,h)
    gemm_tc<128, 64, 32, 32, false, 2, false, true>
        <<<dim3(1, S_ / 128, B_ * NH_), blk>>>(
        attn, Vp, nullptr, Cp, Pp, attn, S_, S_, HD_, 0,
        (long)S_ * S_, (long)S_ * HD_, 0, 1.0f);

    // x = ctx @ Wo^T + bo -> d_out (NT)
    gemm_tc<128, 128, 32, 64, true, 0, false, false>
        <<<dim3(H_ / 128, (B_ * S_) / 128, 1), blk>>>(
        Cp, Wo, bo, xout, nullptr, nullptr, H_, H_, H_, H_, 0, 0, 0, 1.0f);
}

// round 9
// speedup vs baseline: 2.7370x; 1.3047x over previous
#include <cuda_runtime.h>
#include <cstdint>

// Problem constants
#define B_  2
#define S_  4096
#define H_  512
#define NH_ 8
#define HD_ 64
#define XSZ (B_ * S_ * H_)                       // 4,194,304 floats (x output)
#define ASZ ((long)B_ * NH_ * S_ * S_)           // 268,435,456 floats (attention)
#define GXE (S_ / 128)                           // energy col-tiles per row = 32

// Scratch (device globals: the sanctioned allocation-free workaround)
__device__ float g_Q[B_ * NH_ * S_ * HD_];        // tf32-rounded
__device__ float g_K[B_ * NH_ * S_ * HD_];        // tf32-rounded
__device__ float g_V[B_ * NH_ * S_ * HD_];        // tf32-rounded
__device__ float g_ctx[B_ * S_ * H_];             // tf32-rounded
__device__ float g_psum[(long)B_ * NH_ * S_ * GXE];
__device__ float g_attn_fb[(long)B_ * NH_ * S_ * S_];

// ---- helpers ----------------------------------------------------------------
__device__ __forceinline__ float f2tf32(float f) {
    unsigned u;
    asm("cvt.rna.tf32.f32 %0, %1;" : "=r"(u) : "f"(f));
    return __uint_as_float(u);
}
template<bool CVT>
__device__ __forceinline__ unsigned frag(float f) {
    if (CVT) { unsigned u; asm("cvt.rna.tf32.f32 %0, %1;" : "=r"(u) : "f"(f)); return u; }
    return __float_as_uint(f);
}
__device__ __forceinline__ void mma_tf32(float* c, const unsigned* a, const unsigned* b) {
    asm volatile(
        "mma.sync.aligned.m16n8k8.row.col.f32.tf32.tf32.f32 "
        "{%0,%1,%2,%3}, {%4,%5,%6,%7}, {%8,%9}, {%0,%1,%2,%3};"
        : "+f"(c[0]), "+f"(c[1]), "+f"(c[2]), "+f"(c[3])
        : "r"(a[0]), "r"(a[1]), "r"(a[2]), "r"(a[3]), "r"(b[0]), "r"(b[1]));
}
__device__ __forceinline__ unsigned sptr(const void* p) {
    return (unsigned)__cvta_generic_to_shared(p);
}
__device__ __forceinline__ void cp16(unsigned d, const void* s) {
    asm volatile("cp.async.cg.shared.global [%0], [%1], 16;" :: "r"(d), "l"(s));
}
__device__ __forceinline__ void cpcommit() { asm volatile("cp.async.commit_group;"); }
template<int N> __device__ __forceinline__ void cpwait() {
    asm volatile("cp.async.wait_group %0;" :: "n"(N));
}

// ---------------------------------------------------------------------------
// Energy kernel (K = 64, single-shot): attn = exp((Q @ K^T) / 8), unnormalized,
// plus deterministic per-row partial sums psum[(z*S+row)*GXE + blockIdx.x].
// 128x128 tile, 8 warps (4x2), warp tile 32x64. Whole K staged once via
// cp.async -> no mainloop, 1 sync. Q/K are pre-rounded tf32 -> raw fragments.
// ---------------------------------------------------------------------------
__global__ void __launch_bounds__(256, 2) energy_tc(
    const float* __restrict__ Q, const float* __restrict__ Km,
    float* __restrict__ attn, float* __restrict__ psum)
{
    constexpr int LDE = 68;                      // row stride (floats)
    extern __shared__ float sm[];
    float (*As)[LDE] = (float(*)[LDE])sm;
    float (*Bs)[LDE] = (float(*)[LDE])(sm + 128 * LDE);
    __shared__ float rsum[128][2];

    const int z = blockIdx.z;
    Q    += (long)z * S_ * HD_;
    Km   += (long)z * S_ * HD_;
    attn += (long)z * S_ * S_;

    const int m0 = blockIdx.y * 128;
    const int n0 = blockIdx.x * 128;
    const int t = threadIdx.x, warp = t >> 5, lane = t & 31;
    const int wm = warp >> 1, wn = warp & 1;
    const int lr = lane >> 2, lc = lane & 3;

    // ---- single-shot fill: 128 rows x 16 chunks (16B) per operand ----
    {
        const int r  = t >> 1;
        const int cb = (t & 1) * 8;
        unsigned da = sptr(&As[r][cb * 4]);
        unsigned db = sptr(&Bs[r][cb * 4]);
        const float* ga = Q  + (long)(m0 + r) * HD_ + cb * 4;
        const float* gb = Km + (long)(n0 + r) * HD_ + cb * 4;
        #pragma unroll
        for (int j = 0; j < 8; ++j) {
            cp16(da + j * 16, ga + j * 4);
            cp16(db + j * 16, gb + j * 4);
        }
    }
    cpcommit();
    cpwait<0>();
    __syncthreads();

    // ---- compute: 8 k-steps of m16n8k8, raw tf32 fragments ----
    float acc[2][8][4] = {};
    #pragma unroll
    for (int ks = 0; ks < 8; ++ks) {
        const int kc = ks * 8 + lc;
        unsigned a[2][4], b[8][2];
        #pragma unroll
        for (int i = 0; i < 2; ++i) {
            const int row = wm * 32 + i * 16 + lr;
            a[i][0] = __float_as_uint(As[row    ][kc    ]);
            a[i][1] = __float_as_uint(As[row + 8][kc    ]);
            a[i][2] = __float_as_uint(As[row    ][kc + 4]);
            a[i][3] = __float_as_uint(As[row + 8][kc + 4]);
        }
        #pragma unroll
        for (int j = 0; j < 8; ++j) {
            const int col = wn * 64 + j * 8 + lr;
            b[j][0] = __float_as_uint(Bs[col][kc    ]);
            b[j][1] = __float_as_uint(Bs[col][kc + 4]);
        }
        #pragma unroll
        for (int i = 0; i < 2; ++i)
            #pragma unroll
            for (int j = 0; j < 8; ++j)
                mma_tf32(acc[i][j], a[i], b[j]);
    }

    // ---- epilogue: exp(scale*acc), partial row sums, STG ----
    #pragma unroll
    for (int i = 0; i < 2; ++i) {
        const int rr = m0 + wm * 32 + i * 16 + lr;
        float s0 = 0.0f, s1 = 0.0f;
        #pragma unroll
        for (int j = 0; j < 8; ++j) {
            const int cc = n0 + wn * 64 + j * 8 + 2 * lc;
            float e0 = __expf(acc[i][j][0] * 0.125f);
            float e1 = __expf(acc[i][j][1] * 0.125f);
            float e2 = __expf(acc[i][j][2] * 0.125f);
            float e3 = __expf(acc[i][j][3] * 0.125f);
            s0 += e0 + e1;
            s1 += e2 + e3;
            *(float2*)(attn + (long)rr * S_ + cc)       = make_float2(e0, e1);
            *(float2*)(attn + (long)(rr + 8) * S_ + cc) = make_float2(e2, e3);
        }
        s0 += __shfl_xor_sync(0xffffffffu, s0, 1);
        s0 += __shfl_xor_sync(0xffffffffu, s0, 2);
        s1 += __shfl_xor_sync(0xffffffffu, s1, 1);
        s1 += __shfl_xor_sync(0xffffffffu, s1, 2);
        if (lc == 0) {
            rsum[wm * 32 + i * 16 + lr    ][wn] = s0;
            rsum[wm * 32 + i * 16 + 8 + lr][wn] = s1;
        }
    }
    __syncthreads();
    if (t < 128)
        psum[((long)z * S_ + m0 + t) * GXE + blockIdx.x] = rsum[t][0] + rsum[t][1];
}

// ---------------------------------------------------------------------------
// Double-buffered tf32 GEMM (cp.async pipeline): C = scale*(A x B) + bias
//   TM x TN tile, BK=32, 256 threads, warp tile WM x WN, m16n8k8.
//   BNT ? B[N,K] (NT, smem [n][k] stride 36) : B[K,N] (NN, smem [k][n] stride TN+8).
//   CVTA/CVTB: RNA-round fragments post-LDS (for raw-fp32 operands).
//   OUTMODE 0: row-major; 1: head-split [B,NH,S,HD] (tf32-rounds stores);
//   2: per-head AV merged into [B,S,H] (tf32-rounds stores).
//   NORM: A is unnormalized exp; prologue builds inv row sums from psum;
//   staged A tiles are written back normalized (final attention, fp32) and
//   the accumulator is normalized in the epilogue.
// ---------------------------------------------------------------------------
template<int TM, int TN, int WM, int WN, bool BNT, int OUTMODE, bool NORM,
         bool CVTA, bool CVTB>
__global__ void __launch_bounds__(256, 2) gemm_db(
    const float* __restrict__ A, const float* __restrict__ Bm,
    const float* __restrict__ bias, float* __restrict__ C,
    const float* __restrict__ psum, float* __restrict__ Aw,
    int K, int lda, int ldb, int ldc,
    long sAz, long sBz, long sCz, float scale)
{
    constexpr int BK   = 32;
    constexpr int LA   = 36;
    constexpr int LB   = BNT ? 36 : TN + 8;
    constexpr int ABUF = TM * LA;
    constexpr int BBUF = BNT ? TN * LB : BK * LB;
    constexpr int WGN  = TN / WN;
    constexpr int MT   = WM / 16;
    constexpr int NT   = WN / 8;
    static_assert((TM / WM) * WGN == 8, "warp grid must be 8 warps");

    extern __shared__ float sm[];
    float* As = sm;                    // [2][TM][LA]
    float* Bs = sm + 2 * ABUF;         // [2][...]
    __shared__ float inv_s[NORM ? TM : 1];

    const int z = blockIdx.z;
    A  += (long)z * sAz;
    Bm += (long)z * sBz;
    C  += (long)z * sCz;
    if (NORM) Aw += (long)z * sAz;

    const int m0 = blockIdx.y * TM;
    const int n0 = blockIdx.x * TN;
    const int t = threadIdx.x, warp = t >> 5, lane = t & 31;
    const int wm = warp / WGN, wn = warp % WGN;
    const int lr = lane >> 2, lc = lane & 3;

    if (NORM) {
        if (t < TM) {
            const float4* pp = (const float4*)(psum + ((long)z * S_ + m0 + t) * GXE);
            float s = 0.0f;
            #pragma unroll
            for (int q = 0; q < GXE / 4; ++q) {
                float4 v = pp[q];
                s += (v.x + v.y) + (v.z + v.w);
            }
            inv_s[t] = 1.0f / s;
        }
        __syncthreads();
    }

    auto fill = [&](int buf, int k0) {
        #pragma unroll
        for (int s = 0; s < TM * BK / 1024; ++s) {        // A tile
            const int idx = t + 256 * s;
            const int r = idx >> 3, c4 = idx & 7;
            cp16(sptr(As + buf * ABUF + r * LA + c4 * 4),
                 A + (long)(m0 + r) * lda + k0 + c4 * 4);
        }
        if (BNT) {
            #pragma unroll
            for (int s = 0; s < TN * BK / 1024; ++s) {
                const int idx = t + 256 * s;
                const int r = idx >> 3, c4 = idx & 7;
                cp16(sptr(Bs + buf * BBUF + r * LB + c4 * 4),
                     Bm + (long)(n0 + r) * ldb + k0 + c4 * 4);
            }
        } else {
            #pragma unroll
            for (int s = 0; s < BK * TN / 1024; ++s) {
                const int idx = t + 256 * s;
                const int kr = idx / (TN / 4), c4 = idx % (TN / 4);
                cp16(sptr(Bs + buf * BBUF + kr * LB + c4 * 4),
                     Bm + (long)(k0 + kr) * ldb + n0 + c4 * 4);
            }
        }
    };

    float acc[MT][NT][4] = {};
    const int NIT = K / BK;

    fill(0, 0);
    cpcommit();

    for (int it = 0; it < NIT; ++it) {
        const int cur = it & 1;
        if (it + 1 < NIT) {
            fill(cur ^ 1, (it + 1) * BK);
            cpcommit();
            cpwait<1>();
        } else {
            cpwait<0>();
        }
        __syncthreads();

        if (NORM) {
            // mandatory normalized-attention write, streamed from smem
            #pragma unroll
            for (int s = 0; s < TM * BK / 1024; ++s) {
                const int idx = t + 256 * s;
                const int r = idx >> 3, c4 = idx & 7;
                float4 v = *(const float4*)(As + cur * ABUF + r * LA + c4 * 4);
                const float iv = inv_s[r];
                v.x *= iv; v.y *= iv; v.z *= iv; v.w *= iv;
                *(float4*)(Aw + (long)(m0 + r) * lda + it * BK + c4 * 4) = v;
            }
        }

        #pragma unroll
        for (int ks = 0; ks < BK / 8; ++ks) {
            const int kc = ks * 8 + lc;
            unsigned a[MT][4], b[NT][2];
            #pragma unroll
            for (int i = 0; i < MT; ++i) {
                const float* ap = As + cur * ABUF;
                const int row = wm * WM + i * 16 + lr;
                a[i][0] = frag<CVTA>(ap[(row    ) * LA + kc    ]);
                a[i][1] = frag<CVTA>(ap[(row + 8) * LA + kc    ]);
                a[i][2] = frag<CVTA>(ap[(row    ) * LA + kc + 4]);
                a[i][3] = frag<CVTA>(ap[(row + 8) * LA + kc + 4]);
            }
            #pragma unroll
            for (int j = 0; j < NT; ++j) {
                const float* bp = Bs + cur * BBUF;
                const int col = wn * WN + j * 8 + lr;
                if (BNT) {
                    b[j][0] = frag<CVTB>(bp[col * LB + kc    ]);
                    b[j][1] = frag<CVTB>(bp[col * LB + kc + 4]);
                } else {
                    b[j][0] = frag<CVTB>(bp[(kc    ) * LB + col]);
                    b[j][1] = frag<CVTB>(bp[(kc + 4) * LB + col]);
                }
            }
            #pragma unroll
            for (int i = 0; i < MT; ++i)
                #pragma unroll
                for (int j = 0; j < NT; ++j)
                    mma_tf32(acc[i][j], a[i], b[j]);
        }
        __syncthreads();
    }

    // ---- epilogue ----
    #pragma unroll
    for (int i = 0; i < MT; ++i) {
        const int rloc = wm * WM + i * 16 + lr;
        const float iv0 = NORM ? inv_s[rloc]     : 1.0f;
        const float iv1 = NORM ? inv_s[rloc + 8] : 1.0f;
        #pragma unroll
        for (int j = 0; j < NT; ++j) {
            const int rr = m0 + rloc;
            const int cc = n0 + wn * WN + j * 8 + 2 * lc;
            const float b0 = bias ? bias[cc] : 0.0f;
            const float b1 = bias ? bias[cc + 1] : 0.0f;
            float2 v0 = make_float2(acc[i][j][0] * scale * iv0 + b0,
                                    acc[i][j][1] * scale * iv0 + b1);
            float2 v1 = make_float2(acc[i][j][2] * scale * iv1 + b0,
                                    acc[i][j][3] * scale * iv1 + b1);
            if (OUTMODE != 0) {   // scratch consumed by tf32 MMAs: pre-round
                v0.x = f2tf32(v0.x); v0.y = f2tf32(v0.y);
                v1.x = f2tf32(v1.x); v1.y = f2tf32(v1.y);
            }
            #pragma unroll
            for (int h = 0; h < 2; ++h) {
                const int m = rr + h * 8;
                const float2 v = h ? v1 : v0;
                float* dst;
                if (OUTMODE == 1) {
                    const int bb = m / S_, ss = m % S_;
                    const int hh = cc / HD_, dd = cc % HD_;
                    dst = C + (((long)(bb * NH_ + hh) * S_ + ss) * HD_ + dd);
                } else if (OUTMODE == 2) {
                    dst = C + ((long)(z >> 3) * ((long)S_ * H_)
                              + (long)(z & 7) * HD_ + (long)m * H_ + cc);
                } else {
                    dst = C + ((long)m * ldc + cc);
                }
                *(float2*)dst = v;
            }
        }
    }
}

// ---------------------------------------------------------------------------
// kernel_launch
// Inputs: query, key, value, Wq, bq, Wk, bk, Wv, bv, Wo, bo
// Output: [ x (B*S*H) | attention (B*NH*S*S) ]
// ---------------------------------------------------------------------------
extern "C" void kernel_launch(void* const* d_in, const int* in_sizes, int n_in,
                              void* d_out, int out_size)
{
    const float* query = (const float*)d_in[0];
    const float* key_  = (const float*)d_in[1];
    const float* value = (const float*)d_in[2];
    const float* Wq = (const float*)d_in[3];
    const float* bq = (const float*)d_in[4];
    const float* Wk = (const float*)d_in[5];
    const float* bk = (const float*)d_in[6];
    const float* Wv = (const float*)d_in[7];
    const float* bv = (const float*)d_in[8];
    const float* Wo = (const float*)d_in[9];
    const float* bo = (const float*)d_in[10];

    float* xout = (float*)d_out;

    float *Qp, *Kp, *Vp, *Cp, *Pp, *Afb;
    cudaGetSymbolAddress((void**)&Qp, g_Q);
    cudaGetSymbolAddress((void**)&Kp, g_K);
    cudaGetSymbolAddress((void**)&Vp, g_V);
    cudaGetSymbolAddress((void**)&Cp, g_ctx);
    cudaGetSymbolAddress((void**)&Pp, g_psum);
    cudaGetSymbolAddress((void**)&Afb, g_attn_fb);

    float* attn = ((long)out_size >= (long)XSZ + ASZ) ? (xout + XSZ) : Afb;

    // dynamic smem sizes
    const int SM_BNT = 2 * (128 * 36 + 128 * 36) * 4;          // 73728
    const int SM_AV  = (2 * 128 * 36 + 2 * 32 * 72) * 4;       // 55296
    const int SM_EN  = 2 * 128 * 68 * 4;                       // 69632

    auto proj = gemm_db<128, 128, 32, 64, true, 1, false, true, true>;
    auto oprj = gemm_db<128, 128, 32, 64, true, 0, false, false, true>;
    auto avk  = gemm_db<128,  64, 32, 32, false, 2, true, true, false>;

    cudaFuncSetAttribute(proj, cudaFuncAttributeMaxDynamicSharedMemorySize, SM_BNT);
    cudaFuncSetAttribute(oprj, cudaFuncAttributeMaxDynamicSharedMemorySize, SM_BNT);
    cudaFuncSetAttribute(avk,  cudaFuncAttributeMaxDynamicSharedMemorySize, SM_AV);
    cudaFuncSetAttribute(energy_tc, cudaFuncAttributeMaxDynamicSharedMemorySize, SM_EN);

    const dim3 blk(256);

    // Q/K/V projections -> head-split tf32-rounded scratch (NT)
    proj<<<dim3(H_ / 128, (B_ * S_) / 128, 1), blk, SM_BNT>>>(
        query, Wq, bq, Qp, nullptr, nullptr, H_, H_, H_, 0, 0, 0, 0, 1.0f);
    proj<<<dim3(H_ / 128, (B_ * S_) / 128, 1), blk, SM_BNT>>>(
        key_, Wk, bk, Kp, nullptr, nullptr, H_, H_, H_, 0, 0, 0, 0, 1.0f);
    proj<<<dim3(H_ / 128, (B_ * S_) / 128, 1), blk, SM_BNT>>>(
        value, Wv, bv, Vp, nullptr, nullptr, H_, H_, H_, 0, 0, 0, 0, 1.0f);

    // energy + exp (unnormalized) + row partial sums
    energy_tc<<<dim3(S_ / 128, S_ / 128, B_ * NH_), blk, SM_EN>>>(
        Qp, Kp, attn, Pp);

    // ctx = softmax(attn) @ V; writes normalized attention back in place
    avk<<<dim3(1, S_ / 128, B_ * NH_), blk, SM_AV>>>(
        attn, Vp, nullptr, Cp, Pp, attn, S_, S_, HD_, 0,
        (long)S_ * S_, (long)S_ * HD_, 0, 1.0f);

    // x = ctx @ Wo^T + bo -> d_out (NT)
    oprj<<<dim3(H_ / 128, (B_ * S_) / 128, 1), blk, SM_BNT>>>(
        Cp, Wo, bo, xout, nullptr, nullptr, H_, H_, H_, H_, 0, 0, 0, 1.0f);
}

// round 11
// speedup vs baseline: 2.8364x; 1.0363x over previous
#include <cuda_runtime.h>
#include <cstdint>

// Problem constants
#define B_  2
#define S_  4096
#define H_  512
#define NH_ 8
#define HD_ 64
#define XSZ (B_ * S_ * H_)                       // 4,194,304 floats (x output)
#define ASZ ((long)B_ * NH_ * S_ * S_)           // 268,435,456 floats (attention)
#define GXE (S_ / 128)                           // energy col-tiles per row = 32
#define NWALK 8                                  // n-tiles walked per energy CTA

// Scratch (device globals: the sanctioned allocation-free workaround)
__device__ float g_Q[B_ * NH_ * S_ * HD_];        // tf32-rounded
__device__ float g_K[B_ * NH_ * S_ * HD_];        // tf32-rounded
__device__ float g_V[B_ * NH_ * S_ * HD_];        // tf32-rounded
__device__ float g_ctx[B_ * S_ * H_];             // tf32-rounded
__device__ float g_psum[(long)B_ * NH_ * S_ * GXE];
__device__ float g_attn_fb[(long)B_ * NH_ * S_ * S_];

struct PtrSet { const float* A; const float* B; const float* bias; float* C; };

// ---- helpers ----------------------------------------------------------------
__device__ __forceinline__ float f2tf32(float f) {
    unsigned u;
    asm("cvt.rna.tf32.f32 %0, %1;" : "=r"(u) : "f"(f));
    return __uint_as_float(u);
}
template<bool CVT>
__device__ __forceinline__ unsigned frag(float f) {
    if (CVT) { unsigned u; asm("cvt.rna.tf32.f32 %0, %1;" : "=r"(u) : "f"(f)); return u; }
    return __float_as_uint(f);
}
__device__ __forceinline__ void mma_tf32(float* c, const unsigned* a, const unsigned* b) {
    asm volatile(
        "mma.sync.aligned.m16n8k8.row.col.f32.tf32.tf32.f32 "
        "{%0,%1,%2,%3}, {%4,%5,%6,%7}, {%8,%9}, {%0,%1,%2,%3};"
        : "+f"(c[0]), "+f"(c[1]), "+f"(c[2]), "+f"(c[3])
        : "r"(a[0]), "r"(a[1]), "r"(a[2]), "r"(a[3]), "r"(b[0]), "r"(b[1]));
}
__device__ __forceinline__ unsigned sptr(const void* p) {
    return (unsigned)__cvta_generic_to_shared(p);
}
__device__ __forceinline__ void cp16(unsigned d, const void* s) {
    asm volatile("cp.async.cg.shared.global [%0], [%1], 16;" :: "r"(d), "l"(s));
}
__device__ __forceinline__ void cpcommit() { asm volatile("cp.async.commit_group;"); }
template<int N> __device__ __forceinline__ void cpwait() {
    asm volatile("cp.async.wait_group %0;" :: "n"(N));
}

// ---------------------------------------------------------------------------
// Energy kernel, n-walk version.
// Each CTA: one 128-row Q tile (resident in smem for the whole CTA) and a walk
// over NWALK consecutive 128-col K tiles (double-buffered cp.async).
// Per tile: attn = exp((Q @ K^T)/8) (unnormalized) + deterministic per-row
// partial sums psum[(z*S+row)*GXE + (bx*NWALK+nt)].
// Pipeline: fill(K_{nt+1}) and STG-drain of tile nt overlap tile nt+1's MMA.
// Q/K are pre-rounded tf32 -> raw fragments.
// ---------------------------------------------------------------------------
__global__ void __launch_bounds__(256, 2) energy_tc(
    const float* __restrict__ Q, const float* __restrict__ Km,
    float* __restrict__ attn, float* __restrict__ psum)
{
    constexpr int LDE = 68;                      // row stride (floats)
    extern __shared__ float sm[];
    float* Qs = sm;                              // [128][LDE]
    float* Ks = sm + 128 * LDE;                  // [2][128][LDE]
    __shared__ float rsum[128][2];

    const int z = blockIdx.z;
    Q    += (long)z * S_ * HD_;
    Km   += (long)z * S_ * HD_;
    attn += (long)z * S_ * S_;

    const int m0     = blockIdx.y * 128;
    const int n_base = blockIdx.x * (128 * NWALK);
    const int t = threadIdx.x, warp = t >> 5, lane = t & 31;
    const int wm = warp >> 1, wn = warp & 1;
    const int lr = lane >> 2, lc = lane & 3;

    const int fr = t >> 1;                       // fill row (0..127)
    const int fc = (t & 1) * 8;                  // fill chunk base (float4 units)

    auto fillK = [&](int buf, int n0) {
        unsigned db = sptr(Ks + (buf * 128 + fr) * LDE + fc * 4);
        const float* gb = Km + (long)(n0 + fr) * HD_ + fc * 4;
        #pragma unroll
        for (int j = 0; j < 8; ++j) cp16(db + j * 16, gb + j * 4);
    };

    // Q fill (once) + K tile 0, same commit group
    {
        unsigned da = sptr(Qs + fr * LDE + fc * 4);
        const float* ga = Q + (long)(m0 + fr) * HD_ + fc * 4;
        #pragma unroll
        for (int j = 0; j < 8; ++j) cp16(da + j * 16, ga + j * 4);
    }
    fillK(0, n_base);
    cpcommit();

    for (int nt = 0; nt < NWALK; ++nt) {
        const int cur = nt & 1;
        if (nt + 1 < NWALK) {
            fillK(cur ^ 1, n_base + (nt + 1) * 128);
            cpcommit();
            cpwait<1>();
        } else {
            cpwait<0>();
        }
        __syncthreads();

        // ---- MMA: 8 k-steps of m16n8k8, raw tf32 fragments ----
        float acc[2][8][4] = {};
        #pragma unroll
        for (int ks = 0; ks < 8; ++ks) {
            const int kc = ks * 8 + lc;
            unsigned a[2][4], b[8][2];
            #pragma unroll
            for (int i = 0; i < 2; ++i) {
                const float* qp = Qs + (wm * 32 + i * 16 + lr) * LDE;
                a[i][0] = __float_as_uint(qp[kc          ]);
                a[i][1] = __float_as_uint(qp[8 * LDE + kc]);
                a[i][2] = __float_as_uint(qp[kc + 4      ]);
                a[i][3] = __float_as_uint(qp[8 * LDE + kc + 4]);
            }
            #pragma unroll
            for (int j = 0; j < 8; ++j) {
                const float* kp = Ks + (cur * 128 + wn * 64 + j * 8 + lr) * LDE;
                b[j][0] = __float_as_uint(kp[kc    ]);
                b[j][1] = __float_as_uint(kp[kc + 4]);
            }
            #pragma unroll
            for (int i = 0; i < 2; ++i)
                #pragma unroll
                for (int j = 0; j < 8; ++j)
                    mma_tf32(acc[i][j], a[i], b[j]);
        }

        // ---- epilogue: exp(acc/8), partial row sums, STG (drains under
        //      next tile's prefetch + MMA) ----
        const int n0 = n_base + nt * 128;
        #pragma unroll
        for (int i = 0; i < 2; ++i) {
            const int rr = m0 + wm * 32 + i * 16 + lr;
            float s0 = 0.0f, s1 = 0.0f;
            #pragma unroll
            for (int j = 0; j < 8; ++j) {
                const int cc = n0 + wn * 64 + j * 8 + 2 * lc;
                float e0 = __expf(acc[i][j][0] * 0.125f);
                float e1 = __expf(acc[i][j][1] * 0.125f);
                float e2 = __expf(acc[i][j][2] * 0.125f);
                float e3 = __expf(acc[i][j][3] * 0.125f);
                s0 += e0 + e1;
                s1 += e2 + e3;
                *(float2*)(attn + (long)rr * S_ + cc)       = make_float2(e0, e1);
                *(float2*)(attn + (long)(rr + 8) * S_ + cc) = make_float2(e2, e3);
            }
            s0 += __shfl_xor_sync(0xffffffffu, s0, 1);
            s0 += __shfl_xor_sync(0xffffffffu, s0, 2);
            s1 += __shfl_xor_sync(0xffffffffu, s1, 1);
            s1 += __shfl_xor_sync(0xffffffffu, s1, 2);
            if (lc == 0) {
                rsum[wm * 32 + i * 16 + lr    ][wn] = s0;
                rsum[wm * 32 + i * 16 + 8 + lr][wn] = s1;
            }
        }
        // barrier: rsum complete; also guarantees all MMA reads of Ks[cur]
        // are done before the next iteration's fillK overwrites it.
        __syncthreads();
        if (t < 128)
            psum[((long)z * S_ + m0 + t) * GXE + blockIdx.x * NWALK + nt] =
                rsum[t][0] + rsum[t][1];
    }
}

// ---------------------------------------------------------------------------
// Double-buffered tf32 GEMM (cp.async pipeline): C = scale*(A x B) + bias
//   TM x TN tile, BK=32, 256 threads, warp tile WM x WN, m16n8k8.
//   BNT ? B[N,K] (NT, smem [n][k] stride 36) : B[K,N] (NN, smem [k][n] stride TN+8).
//   CVTA/CVTB: RNA-round fragments post-LDS (for raw-fp32 operands).
//   OUTMODE 0: row-major; 1: head-split [B,NH,S,HD]; 2: per-head AV merged
//   into [B,S,H]. OUTMODE!=0 tf32-rounds stores (consumed by later MMAs).
//   NORM: A is unnormalized exp; prologue builds inv row sums from psum;
//   staged A tiles are written back normalized (final attention) and the
//   accumulator is normalized in the epilogue.
//   MERGE3: z in {0,1,2} selects pointer set p0/p1/p2 (independent GEMMs in
//   one launch); otherwise z applies the sAz/sBz/sCz batch offsets to p0.
// ---------------------------------------------------------------------------
template<int TM, int TN, int WM, int WN, bool BNT, int OUTMODE, bool NORM,
         bool CVTA, bool CVTB, bool MERGE3>
__global__ void __launch_bounds__(256, 2) gemm_db(
    PtrSet p0, PtrSet p1, PtrSet p2,
    const float* __restrict__ psum, float* __restrict__ Aw,
    int K, int lda, int ldb, int ldc,
    long sAz, long sBz, long sCz, float scale)
{
    constexpr int BK   = 32;
    constexpr int LA   = 36;
    constexpr int LB   = BNT ? 36 : TN + 8;
    constexpr int ABUF = TM * LA;
    constexpr int BBUF = BNT ? TN * LB : BK * LB;
    constexpr int WGN  = TN / WN;
    constexpr int MT   = WM / 16;
    constexpr int NT   = WN / 8;
    static_assert((TM / WM) * WGN == 8, "warp grid must be 8 warps");

    extern __shared__ float sm[];
    float* As = sm;                    // [2][TM][LA]
    float* Bs = sm + 2 * ABUF;         // [2][...]
    __shared__ float inv_s[NORM ? TM : 1];

    const int z = blockIdx.z;
    PtrSet P = p0;
    if (MERGE3) { if (z == 1) P = p1; else if (z == 2) P = p2; }
    const float* A  = P.A;
    const float* Bm = P.B;
    const float* bias = P.bias;
    float* C = P.C;
    if (!MERGE3) {
        A  += (long)z * sAz;
        Bm += (long)z * sBz;
        C  += (long)z * sCz;
        if (NORM) Aw += (long)z * sAz;
    }

    const int m0 = blockIdx.y * TM;
    const int n0 = blockIdx.x * TN;
    const int t = threadIdx.x, warp = t >> 5, lane = t & 31;
    const int wm = warp / WGN, wn = warp % WGN;
    const int lr = lane >> 2, lc = lane & 3;

    if (NORM) {
        if (t < TM) {
            const float4* pp = (const float4*)(psum + ((long)z * S_ + m0 + t) * GXE);
            float s = 0.0f;
            #pragma unroll
            for (int q = 0; q < GXE / 4; ++q) {
                float4 v = pp[q];
                s += (v.x + v.y) + (v.z + v.w);
            }
            inv_s[t] = 1.0f / s;
        }
        __syncthreads();
    }

    auto fill = [&](int buf, int k0) {
        #pragma unroll
        for (int s = 0; s < TM * BK / 1024; ++s) {        // A tile
            const int idx = t + 256 * s;
            const int r = idx >> 3, c4 = idx & 7;
            cp16(sptr(As + buf * ABUF + r * LA + c4 * 4),
                 A + (long)(m0 + r) * lda + k0 + c4 * 4);
        }
        if (BNT) {
            #pragma unroll
            for (int s = 0; s < TN * BK / 1024; ++s) {
                const int idx = t + 256 * s;
                const int r = idx >> 3, c4 = idx & 7;
                cp16(sptr(Bs + buf * BBUF + r * LB + c4 * 4),
                     Bm + (long)(n0 + r) * ldb + k0 + c4 * 4);
            }
        } else {
            #pragma unroll
            for (int s = 0; s < BK * TN / 1024; ++s) {
                const int idx = t + 256 * s;
                const int kr = idx / (TN / 4), c4 = idx % (TN / 4);
                cp16(sptr(Bs + buf * BBUF + kr * LB + c4 * 4),
                     Bm + (long)(k0 + kr) * ldb + n0 + c4 * 4);
            }
        }
    };

    float acc[MT][NT][4] = {};
    const int NIT = K / BK;

    fill(0, 0);
    cpcommit();

    for (int it = 0; it < NIT; ++it) {
        const int cur = it & 1;
        if (it + 1 < NIT) {
            fill(cur ^ 1, (it + 1) * BK);
            cpcommit();
            cpwait<1>();
        } else {
            cpwait<0>();
        }
        __syncthreads();

        if (NORM) {
            // mandatory normalized-attention write, streamed from smem
            #pragma unroll
            for (int s = 0; s < TM * BK / 1024; ++s) {
                const int idx = t + 256 * s;
                const int r = idx >> 3, c4 = idx & 7;
                float4 v = *(const float4*)(As + cur * ABUF + r * LA + c4 * 4);
                const float iv = inv_s[r];
                v.x *= iv; v.y *= iv; v.z *= iv; v.w *= iv;
                *(float4*)(Aw + (long)(m0 + r) * lda + it * BK + c4 * 4) = v;
            }
        }

        #pragma unroll
        for (int ks = 0; ks < BK / 8; ++ks) {
            const int kc = ks * 8 + lc;
            unsigned a[MT][4], b[NT][2];
            #pragma unroll
            for (int i = 0; i < MT; ++i) {
                const float* ap = As + cur * ABUF;
                const int row = wm * WM + i * 16 + lr;
                a[i][0] = frag<CVTA>(ap[(row    ) * LA + kc    ]);
                a[i][1] = frag<CVTA>(ap[(row + 8) * LA + kc    ]);
                a[i][2] = frag<CVTA>(ap[(row    ) * LA + kc + 4]);
                a[i][3] = frag<CVTA>(ap[(row + 8) * LA + kc + 4]);
            }
            #pragma unroll
            for (int j = 0; j < NT; ++j) {
                const float* bp = Bs + cur * BBUF;
                const int col = wn * WN + j * 8 + lr;
                if (BNT) {
                    b[j][0] = frag<CVTB>(bp[col * LB + kc    ]);
                    b[j][1] = frag<CVTB>(bp[col * LB + kc + 4]);
                } else {
                    b[j][0] = frag<CVTB>(bp[(kc    ) * LB + col]);
                    b[j][1] = frag<CVTB>(bp[(kc + 4) * LB + col]);
                }
            }
            #pragma unroll
            for (int i = 0; i < MT; ++i)
                #pragma unroll
                for (int j = 0; j < NT; ++j)
                    mma_tf32(acc[i][j], a[i], b[j]);
        }
        __syncthreads();
    }

    // ---- epilogue ----
    #pragma unroll
    for (int i = 0; i < MT; ++i) {
        const int rloc = wm * WM + i * 16 + lr;
        const float iv0 = NORM ? inv_s[rloc]     : 1.0f;
        const float iv1 = NORM ? inv_s[rloc + 8] : 1.0f;
        #pragma unroll
        for (int j = 0; j < NT; ++j) {
            const int rr = m0 + rloc;
            const int cc = n0 + wn * WN + j * 8 + 2 * lc;
            const float b0 = bias ? bias[cc] : 0.0f;
            const float b1 = bias ? bias[cc + 1] : 0.0f;
            float2 v0 = make_float2(acc[i][j][0] * scale * iv0 + b0,
                                    acc[i][j][1] * scale * iv0 + b1);
            float2 v1 = make_float2(acc[i][j][2] * scale * iv1 + b0,
                                    acc[i][j][3] * scale * iv1 + b1);
            if (OUTMODE != 0) {   // scratch consumed by tf32 MMAs: pre-round
                v0.x = f2tf32(v0.x); v0.y = f2tf32(v0.y);
                v1.x = f2tf32(v1.x); v1.y = f2tf32(v1.y);
            }
            #pragma unroll
            for (int h = 0; h < 2; ++h) {
                const int m = rr + h * 8;
                const float2 v = h ? v1 : v0;
                float* dst;
                if (OUTMODE == 1) {
                    const int bb = m / S_, ss = m % S_;
                    const int hh = cc / HD_, dd = cc % HD_;
                    dst = C + (((long)(bb * NH_ + hh) * S_ + ss) * HD_ + dd);
                } else if (OUTMODE == 2) {
                    dst = C + ((long)(z >> 3) * ((long)S_ * H_)
                              + (long)(z & 7) * HD_ + (long)m * H_ + cc);
                } else {
                    dst = C + ((long)m * ldc + cc);
                }
                *(float2*)dst = v;
            }
        }
    }
}

// ---------------------------------------------------------------------------
// kernel_launch
// Inputs: query, key, value, Wq, bq, Wk, bk, Wv, bv, Wo, bo
// Output: [ x (B*S*H) | attention (B*NH*S*S) ]
// ---------------------------------------------------------------------------
extern "C" void kernel_launch(void* const* d_in, const int* in_sizes, int n_in,
                              void* d_out, int out_size)
{
    const float* query = (const float*)d_in[0];
    const float* key_  = (const float*)d_in[1];
    const float* value = (const float*)d_in[2];
    const float* Wq = (const float*)d_in[3];
    const float* bq = (const float*)d_in[4];
    const float* Wk = (const float*)d_in[5];
    const float* bk = (const float*)d_in[6];
    const float* Wv = (const float*)d_in[7];
    const float* bv = (const float*)d_in[8];
    const float* Wo = (const float*)d_in[9];
    const float* bo = (const float*)d_in[10];

    float* xout = (float*)d_out;

    float *Qp, *Kp, *Vp, *Cp, *Pp, *Afb;
    cudaGetSymbolAddress((void**)&Qp, g_Q);
    cudaGetSymbolAddress((void**)&Kp, g_K);
    cudaGetSymbolAddress((void**)&Vp, g_V);
    cudaGetSymbolAddress((void**)&Cp, g_ctx);
    cudaGetSymbolAddress((void**)&Pp, g_psum);
    cudaGetSymbolAddress((void**)&Afb, g_attn_fb);

    float* attn = ((long)out_size >= (long)XSZ + ASZ) ? (xout + XSZ) : Afb;

    // dynamic smem sizes
    const int SM_BNT = 2 * (128 * 36 + 128 * 36) * 4;          // 73728
    const int SM_AV  = (2 * 128 * 36 + 2 * 32 * 72) * 4;       // 55296
    const int SM_EN  = (128 + 256) * 68 * 4;                   // 104448

    auto proj = gemm_db<128, 128, 32, 64, true, 1, false, true, true, true>;
    auto oprj = gemm_db<128, 128, 32, 64, true, 0, false, false, true, false>;
    auto avk  = gemm_db<128,  64, 32, 32, false, 2, true, true, false, false>;

    cudaFuncSetAttribute(proj, cudaFuncAttributeMaxDynamicSharedMemorySize, SM_BNT);
    cudaFuncSetAttribute(oprj, cudaFuncAttributeMaxDynamicSharedMemorySize, SM_BNT);
    cudaFuncSetAttribute(avk,  cudaFuncAttributeMaxDynamicSharedMemorySize, SM_AV);
    cudaFuncSetAttribute(energy_tc, cudaFuncAttributeMaxDynamicSharedMemorySize, SM_EN);

    const dim3 blk(256);
    const PtrSet P0{query, Wq, bq, Qp};
    const PtrSet P1{key_,  Wk, bk, Kp};
    const PtrSet P2{value, Wv, bv, Vp};
    const PtrSet PO{Cp,    Wo, bo, xout};
    const PtrSet PA{attn,  Vp, nullptr, Cp};
    const PtrSet PN{nullptr, nullptr, nullptr, nullptr};

    // Q/K/V projections merged into ONE launch (z selects the pointer set)
    proj<<<dim3(H_ / 128, (B_ * S_) / 128, 3), blk, SM_BNT>>>(
        P0, P1, P2, nullptr, nullptr, H_, H_, H_, 0, 0, 0, 0, 1.0f);

    // energy + exp (unnormalized) + row partial sums, n-walk of 8 tiles
    energy_tc<<<dim3(S_ / (128 * NWALK), S_ / 128, B_ * NH_), blk, SM_EN>>>(
        Qp, Kp, attn, Pp);

    // ctx = softmax(attn) @ V; writes normalized attention back in place
    avk<<<dim3(1, S_ / 128, B_ * NH_), blk, SM_AV>>>(
        PA, PN, PN, Pp, attn, S_, S_, HD_, 0,
        (long)S_ * S_, (long)S_ * HD_, 0, 1.0f);

    // x = ctx @ Wo^T + bo -> d_out (NT)
    oprj<<<dim3(H_ / 128, (B_ * S_) / 128, 1), blk, SM_BNT>>>(
        PO, PN, PN, nullptr, nullptr, H_, H_, H_, H_, 0, 0, 0, 1.0f);
}

// round 13
// speedup vs baseline: 2.8702x; 1.0119x over previous
#include <cuda_runtime.h>
#include <cstdint>

// Problem constants
#define B_  2
#define S_  4096
#define H_  512
#define NH_ 8
#define HD_ 64
#define XSZ (B_ * S_ * H_)                       // 4,194,304 floats (x output)
#define ASZ ((long)B_ * NH_ * S_ * S_)           // 268,435,456 floats (attention)
#define GXE (S_ / 128)                           // energy col-tiles per row = 32
#define NWALK 8                                  // n-tiles walked per energy CTA

// Scratch (device globals: the sanctioned allocation-free workaround)
__device__ float g_Q[B_ * NH_ * S_ * HD_];        // tf32-rounded
__device__ float g_K[B_ * NH_ * S_ * HD_];        // tf32-rounded
__device__ float g_V[B_ * NH_ * S_ * HD_];        // tf32-rounded
__device__ float g_ctx[B_ * S_ * H_];             // tf32-rounded
__device__ float g_psum[(long)B_ * NH_ * S_ * GXE];
__device__ float g_attn_fb[(long)B_ * NH_ * S_ * S_];

struct PtrSet { const float* A; const float* B; const float* bias; float* C; };

// ---- helpers ----------------------------------------------------------------
__device__ __forceinline__ float f2tf32(float f) {
    unsigned u;
    asm("cvt.rna.tf32.f32 %0, %1;" : "=r"(u) : "f"(f));
    return __uint_as_float(u);
}
template<bool CVT>
__device__ __forceinline__ unsigned frag(float f) {
    if (CVT) { unsigned u; asm("cvt.rna.tf32.f32 %0, %1;" : "=r"(u) : "f"(f)); return u; }
    return __float_as_uint(f);
}
__device__ __forceinline__ void mma_tf32(float* c, const unsigned* a, const unsigned* b) {
    asm volatile(
        "mma.sync.aligned.m16n8k8.row.col.f32.tf32.tf32.f32 "
        "{%0,%1,%2,%3}, {%4,%5,%6,%7}, {%8,%9}, {%0,%1,%2,%3};"
        : "+f"(c[0]), "+f"(c[1]), "+f"(c[2]), "+f"(c[3])
        : "r"(a[0]), "r"(a[1]), "r"(a[2]), "r"(a[3]), "r"(b[0]), "r"(b[1]));
}
__device__ __forceinline__ unsigned sptr(const void* p) {
    return (unsigned)__cvta_generic_to_shared(p);
}
__device__ __forceinline__ void cp16(unsigned d, const void* s) {
    asm volatile("cp.async.cg.shared.global [%0], [%1], 16;" :: "r"(d), "l"(s));
}
__device__ __forceinline__ void cpcommit() { asm volatile("cp.async.commit_group;"); }
template<int N> __device__ __forceinline__ void cpwait() {
    asm volatile("cp.async.wait_group %0;" :: "n"(N));
}

// ---------------------------------------------------------------------------
// Energy kernel, n-walk + j-pipelined version.
// Each CTA: one 128-row Q tile, fragments hoisted to REGISTERS once (64 regs),
// then a walk over NWALK 128-col K tiles (double-buffered cp.async).
// Per tile, the 8 n-subtiles are software-pipelined: MMA(j) issues, then the
// epilogue (exp + STG + rowsum) of subtile j-1 runs while the tensor pipe
// drains -> MUFU/STG overlap HMMA instead of serializing after it.
// attn = exp((Q @ K^T)/8) (unnormalized); deterministic per-row partial sums
// psum[(z*S+row)*GXE + (bx*NWALK+nt)].
// ---------------------------------------------------------------------------
__global__ void __launch_bounds__(256, 2) energy_tc(
    const float* __restrict__ Q, const float* __restrict__ Km,
    float* __restrict__ attn, float* __restrict__ psum)
{
    constexpr int LDE = 68;                      // row stride (floats)
    extern __shared__ float sm[];
    float* Qs = sm;                              // [128][LDE] (used once)
    float* Ks = sm + 128 * LDE;                  // [2][128][LDE]
    __shared__ float rsum[128][2];

    const int z = blockIdx.z;
    Q    += (long)z * S_ * HD_;
    Km   += (long)z * S_ * HD_;
    attn += (long)z * S_ * S_;

    const int m0     = blockIdx.y * 128;
    const int n_base = blockIdx.x * (128 * NWALK);
    const int t = threadIdx.x, warp = t >> 5, lane = t & 31;
    const int wm = warp >> 1, wn = warp & 1;
    const int lr = lane >> 2, lc = lane & 3;

    const int fr = t >> 1;                       // fill row (0..127)
    const int fc = (t & 1) * 8;                  // fill chunk base (float4 units)

    auto fillK = [&](int buf, int n0) {
        unsigned db = sptr(Ks + (buf * 128 + fr) * LDE + fc * 4);
        const float* gb = Km + (long)(n0 + fr) * HD_ + fc * 4;
        #pragma unroll
        for (int j = 0; j < 8; ++j) cp16(db + j * 16, gb + j * 4);
    };

    // Q fill (once) + K tile 0, one commit group
    {
        unsigned da = sptr(Qs + fr * LDE + fc * 4);
        const float* ga = Q + (long)(m0 + fr) * HD_ + fc * 4;
        #pragma unroll
        for (int j = 0; j < 8; ++j) cp16(da + j * 16, ga + j * 4);
    }
    fillK(0, n_base);
    cpcommit();
    cpwait<0>();
    __syncthreads();

    // ---- hoist Q fragments to registers (once per CTA) ----
    unsigned qa[8][2][4];
    #pragma unroll
    for (int ks = 0; ks < 8; ++ks) {
        const int kc = ks * 8 + lc;
        #pragma unroll
        for (int i = 0; i < 2; ++i) {
            const float* qp = Qs + (wm * 32 + i * 16 + lr) * LDE;
            qa[ks][i][0] = __float_as_uint(qp[kc              ]);
            qa[ks][i][1] = __float_as_uint(qp[8 * LDE + kc    ]);
            qa[ks][i][2] = __float_as_uint(qp[kc + 4          ]);
            qa[ks][i][3] = __float_as_uint(qp[8 * LDE + kc + 4]);
        }
    }

    for (int nt = 0; nt < NWALK; ++nt) {
        const int cur = nt & 1;
        if (nt + 1 < NWALK) {
            fillK(cur ^ 1, n_base + (nt + 1) * 128);
            cpcommit();
            cpwait<1>();
        } else {
            cpwait<0>();
        }
        __syncthreads();

        const int n0 = n_base + nt * 128;
        float sum[2][2] = {};                    // [i][rows lr / lr+8]
        float acc[2][2][4];                      // [j&1][i][4]

        // epilogue of subtile jj (acc slot jb): exp, STG, rowsum accumulate
        auto epi = [&](int jj, int jb) {
            const int cc = n0 + wn * 64 + jj * 8 + 2 * lc;
            #pragma unroll
            for (int i = 0; i < 2; ++i) {
                const int rr = m0 + wm * 32 + i * 16 + lr;
                float e0 = __expf(acc[jb][i][0] * 0.125f);
                float e1 = __expf(acc[jb][i][1] * 0.125f);
                float e2 = __expf(acc[jb][i][2] * 0.125f);
                float e3 = __expf(acc[jb][i][3] * 0.125f);
                sum[i][0] += e0 + e1;
                sum[i][1] += e2 + e3;
                *(float2*)(attn + (long)rr * S_ + cc)       = make_float2(e0, e1);
                *(float2*)(attn + (long)(rr + 8) * S_ + cc) = make_float2(e2, e3);
            }
        };

        // ---- j-pipelined MMA: issue MMAs of j, then drain epilogue of j-1 ----
        #pragma unroll
        for (int j = 0; j < 8; ++j) {
            const int jb = j & 1;
            #pragma unroll
            for (int i = 0; i < 2; ++i)
                #pragma unroll
                for (int q = 0; q < 4; ++q) acc[jb][i][q] = 0.0f;

            const float* kp = Ks + (cur * 128 + wn * 64 + j * 8 + lr) * LDE;
            #pragma unroll
            for (int ks = 0; ks < 8; ++ks) {
                const int kc = ks * 8 + lc;
                unsigned b[2] = { __float_as_uint(kp[kc    ]),
                                  __float_as_uint(kp[kc + 4]) };
                mma_tf32(acc[jb][0], qa[ks][0], b);
                mma_tf32(acc[jb][1], qa[ks][1], b);
            }
            if (j > 0) epi(j - 1, jb ^ 1);
        }
        epi(7, 1);

        // ---- row-sum reduce (4 lanes share each row) ----
        #pragma unroll
        for (int i = 0; i < 2; ++i) {
            float s0 = sum[i][0], s1 = sum[i][1];
            s0 += __shfl_xor_sync(0xffffffffu, s0, 1);
            s0 += __shfl_xor_sync(0xffffffffu, s0, 2);
            s1 += __shfl_xor_sync(0xffffffffu, s1, 1);
            s1 += __shfl_xor_sync(0xffffffffu, s1, 2);
            if (lc == 0) {
                rsum[wm * 32 + i * 16 + lr    ][wn] = s0;
                rsum[wm * 32 + i * 16 + 8 + lr][wn] = s1;
            }
        }
        // barrier: rsum complete; also guarantees all MMA reads of Ks[cur]
        // are done before the next iteration's fillK overwrites the peer buf.
        __syncthreads();
        if (t < 128)
            psum[((long)z * S_ + m0 + t) * GXE + blockIdx.x * NWALK + nt] =
                rsum[t][0] + rsum[t][1];
    }
}

// ---------------------------------------------------------------------------
// Double-buffered tf32 GEMM (cp.async pipeline): C = scale*(A x B) + bias
//   TM x TN tile, BK=32, 256 threads, warp tile WM x WN, m16n8k8.
//   BNT ? B[N,K] (NT, smem [n][k] stride 36) : B[K,N] (NN, smem [k][n] stride TN+8).
//   CVTA/CVTB: RNA-round fragments post-LDS (for raw-fp32 operands).
//   OUTMODE 0: row-major; 1: head-split [B,NH,S,HD]; 2: per-head AV merged
//   into [B,S,H]. OUTMODE!=0 tf32-rounds stores (consumed by later MMAs).
//   NORM: A is unnormalized exp; prologue builds inv row sums from psum;
//   staged A tiles are written back normalized (final attention) and the
//   accumulator is normalized in the epilogue.
//   MERGE3: z in {0,1,2} selects pointer set p0/p1/p2 (independent GEMMs in
//   one launch); otherwise z applies the sAz/sBz/sCz batch offsets to p0.
// ---------------------------------------------------------------------------
template<int TM, int TN, int WM, int WN, bool BNT, int OUTMODE, bool NORM,
         bool CVTA, bool CVTB, bool MERGE3>
__global__ void __launch_bounds__(256, 2) gemm_db(
    PtrSet p0, PtrSet p1, PtrSet p2,
    const float* __restrict__ psum, float* __restrict__ Aw,
    int K, int lda, int ldb, int ldc,
    long sAz, long sBz, long sCz, float scale)
{
    constexpr int BK   = 32;
    constexpr int LA   = 36;
    constexpr int LB   = BNT ? 36 : TN + 8;
    constexpr int ABUF = TM * LA;
    constexpr int BBUF = BNT ? TN * LB : BK * LB;
    constexpr int WGN  = TN / WN;
    constexpr int MT   = WM / 16;
    constexpr int NT   = WN / 8;
    static_assert((TM / WM) * WGN == 8, "warp grid must be 8 warps");

    extern __shared__ float sm[];
    float* As = sm;                    // [2][TM][LA]
    float* Bs = sm + 2 * ABUF;         // [2][...]
    __shared__ float inv_s[NORM ? TM : 1];

    const int z = blockIdx.z;
    PtrSet P = p0;
    if (MERGE3) { if (z == 1) P = p1; else if (z == 2) P = p2; }
    const float* A  = P.A;
    const float* Bm = P.B;
    const float* bias = P.bias;
    float* C = P.C;
    if (!MERGE3) {
        A  += (long)z * sAz;
        Bm += (long)z * sBz;
        C  += (long)z * sCz;
        if (NORM) Aw += (long)z * sAz;
    }

    const int m0 = blockIdx.y * TM;
    const int n0 = blockIdx.x * TN;
    const int t = threadIdx.x, warp = t >> 5, lane = t & 31;
    const int wm = warp / WGN, wn = warp % WGN;
    const int lr = lane >> 2, lc = lane & 3;

    if (NORM) {
        if (t < TM) {
            const float4* pp = (const float4*)(psum + ((long)z * S_ + m0 + t) * GXE);
            float s = 0.0f;
            #pragma unroll
            for (int q = 0; q < GXE / 4; ++q) {
                float4 v = pp[q];
                s += (v.x + v.y) + (v.z + v.w);
            }
            inv_s[t] = 1.0f / s;
        }
        __syncthreads();
    }

    auto fill = [&](int buf, int k0) {
        #pragma unroll
        for (int s = 0; s < TM * BK / 1024; ++s) {        // A tile
            const int idx = t + 256 * s;
            const int r = idx >> 3, c4 = idx & 7;
            cp16(sptr(As + buf * ABUF + r * LA + c4 * 4),
                 A + (long)(m0 + r) * lda + k0 + c4 * 4);
        }
        if (BNT) {
            #pragma unroll
            for (int s = 0; s < TN * BK / 1024; ++s) {
                const int idx = t + 256 * s;
                const int r = idx >> 3, c4 = idx & 7;
                cp16(sptr(Bs + buf * BBUF + r * LB + c4 * 4),
                     Bm + (long)(n0 + r) * ldb + k0 + c4 * 4);
            }
        } else {
            #pragma unroll
            for (int s = 0; s < BK * TN / 1024; ++s) {
                const int idx = t + 256 * s;
                const int kr = idx / (TN / 4), c4 = idx % (TN / 4);
                cp16(sptr(Bs + buf * BBUF + kr * LB + c4 * 4),
                     Bm + (long)(k0 + kr) * ldb + n0 + c4 * 4);
            }
        }
    };

    float acc[MT][NT][4] = {};
    const int NIT = K / BK;

    fill(0, 0);
    cpcommit();

    for (int it = 0; it < NIT; ++it) {
        const int cur = it & 1;
        if (it + 1 < NIT) {
            fill(cur ^ 1, (it + 1) * BK);
            cpcommit();
            cpwait<1>();
        } else {
            cpwait<0>();
        }
        __syncthreads();

        if (NORM) {
            // mandatory normalized-attention write, streamed from smem
            #pragma unroll
            for (int s = 0; s < TM * BK / 1024; ++s) {
                const int idx = t + 256 * s;
                const int r = idx >> 3, c4 = idx & 7;
                float4 v = *(const float4*)(As + cur * ABUF + r * LA + c4 * 4);
                const float iv = inv_s[r];
                v.x *= iv; v.y *= iv; v.z *= iv; v.w *= iv;
                *(float4*)(Aw + (long)(m0 + r) * lda + it * BK + c4 * 4) = v;
            }
        }

        #pragma unroll
        for (int ks = 0; ks < BK / 8; ++ks) {
            const int kc = ks * 8 + lc;
            unsigned a[MT][4], b[NT][2];
            #pragma unroll
            for (int i = 0; i < MT; ++i) {
                const float* ap = As + cur * ABUF;
                const int row = wm * WM + i * 16 + lr;
                a[i][0] = frag<CVTA>(ap[(row    ) * LA + kc    ]);
                a[i][1] = frag<CVTA>(ap[(row + 8) * LA + kc    ]);
                a[i][2] = frag<CVTA>(ap[(row    ) * LA + kc + 4]);
                a[i][3] = frag<CVTA>(ap[(row + 8) * LA + kc + 4]);
            }
            #pragma unroll
            for (int j = 0; j < NT; ++j) {
                const float* bp = Bs + cur * BBUF;
                const int col = wn * WN + j * 8 + lr;
                if (BNT) {
                    b[j][0] = frag<CVTB>(bp[col * LB + kc    ]);
                    b[j][1] = frag<CVTB>(bp[col * LB + kc + 4]);
                } else {
                    b[j][0] = frag<CVTB>(bp[(kc    ) * LB + col]);
                    b[j][1] = frag<CVTB>(bp[(kc + 4) * LB + col]);
                }
            }
            #pragma unroll
            for (int i = 0; i < MT; ++i)
                #pragma unroll
                for (int j = 0; j < NT; ++j)
                    mma_tf32(acc[i][j], a[i], b[j]);
        }
        __syncthreads();
    }

    // ---- epilogue ----
    #pragma unroll
    for (int i = 0; i < MT; ++i) {
        const int rloc = wm * WM + i * 16 + lr;
        const float iv0 = NORM ? inv_s[rloc]     : 1.0f;
        const float iv1 = NORM ? inv_s[rloc + 8] : 1.0f;
        #pragma unroll
        for (int j = 0; j < NT; ++j) {
            const int rr = m0 + rloc;
            const int cc = n0 + wn * WN + j * 8 + 2 * lc;
            const float b0 = bias ? bias[cc] : 0.0f;
            const float b1 = bias ? bias[cc + 1] : 0.0f;
            float2 v0 = make_float2(acc[i][j][0] * scale * iv0 + b0,
                                    acc[i][j][1] * scale * iv0 + b1);
            float2 v1 = make_float2(acc[i][j][2] * scale * iv1 + b0,
                                    acc[i][j][3] * scale * iv1 + b1);
            if (OUTMODE != 0) {   // scratch consumed by tf32 MMAs: pre-round
                v0.x = f2tf32(v0.x); v0.y = f2tf32(v0.y);
                v1.x = f2tf32(v1.x); v1.y = f2tf32(v1.y);
            }
            #pragma unroll
            for (int h = 0; h < 2; ++h) {
                const int m = rr + h * 8;
                const float2 v = h ? v1 : v0;
                float* dst;
                if (OUTMODE == 1) {
                    const int bb = m / S_, ss = m % S_;
                    const int hh = cc / HD_, dd = cc % HD_;
                    dst = C + (((long)(bb * NH_ + hh) * S_ + ss) * HD_ + dd);
                } else if (OUTMODE == 2) {
                    dst = C + ((long)(z >> 3) * ((long)S_ * H_)
                              + (long)(z & 7) * HD_ + (long)m * H_ + cc);
                } else {
                    dst = C + ((long)m * ldc + cc);
                }
                *(float2*)dst = v;
            }
        }
    }
}

// ---------------------------------------------------------------------------
// kernel_launch
// Inputs: query, key, value, Wq, bq, Wk, bk, Wv, bv, Wo, bo
// Output: [ x (B*S*H) | attention (B*NH*S*S) ]
// ---------------------------------------------------------------------------
extern "C" void kernel_launch(void* const* d_in, const int* in_sizes, int n_in,
                              void* d_out, int out_size)
{
    const float* query = (const float*)d_in[0];
    const float* key_  = (const float*)d_in[1];
    const float* value = (const float*)d_in[2];
    const float* Wq = (const float*)d_in[3];
    const float* bq = (const float*)d_in[4];
    const float* Wk = (const float*)d_in[5];
    const float* bk = (const float*)d_in[6];
    const float* Wv = (const float*)d_in[7];
    const float* bv = (const float*)d_in[8];
    const float* Wo = (const float*)d_in[9];
    const float* bo = (const float*)d_in[10];

    float* xout = (float*)d_out;

    float *Qp, *Kp, *Vp, *Cp, *Pp, *Afb;
    cudaGetSymbolAddress((void**)&Qp, g_Q);
    cudaGetSymbolAddress((void**)&Kp, g_K);
    cudaGetSymbolAddress((void**)&Vp, g_V);
    cudaGetSymbolAddress((void**)&Cp, g_ctx);
    cudaGetSymbolAddress((void**)&Pp, g_psum);
    cudaGetSymbolAddress((void**)&Afb, g_attn_fb);

    float* attn = ((long)out_size >= (long)XSZ + ASZ) ? (xout + XSZ) : Afb;

    // dynamic smem sizes
    const int SM_BNT = 2 * (128 * 36 + 128 * 36) * 4;          // 73728
    const int SM_AV  = (2 * 128 * 36 + 2 * 32 * 72) * 4;       // 55296
    const int SM_EN  = (128 + 256) * 68 * 4;                   // 104448

    auto proj = gemm_db<128, 128, 32, 64, true, 1, false, true, true, true>;
    auto oprj = gemm_db<128, 128, 32, 64, true, 0, false, false, true, false>;
    auto avk  = gemm_db<128,  64, 32, 32, false, 2, true, true, false, false>;

    cudaFuncSetAttribute(proj, cudaFuncAttributeMaxDynamicSharedMemorySize, SM_BNT);
    cudaFuncSetAttribute(oprj, cudaFuncAttributeMaxDynamicSharedMemorySize, SM_BNT);
    cudaFuncSetAttribute(avk,  cudaFuncAttributeMaxDynamicSharedMemorySize, SM_AV);
    cudaFuncSetAttribute(energy_tc, cudaFuncAttributeMaxDynamicSharedMemorySize, SM_EN);

    const dim3 blk(256);
    const PtrSet P0{query, Wq, bq, Qp};
    const PtrSet P1{key_,  Wk, bk, Kp};
    const PtrSet P2{value, Wv, bv, Vp};
    const PtrSet PO{Cp,    Wo, bo, xout};
    const PtrSet PA{attn,  Vp, nullptr, Cp};
    const PtrSet PN{nullptr, nullptr, nullptr, nullptr};

    // Q/K/V projections merged into ONE launch (z selects the pointer set)
    proj<<<dim3(H_ / 128, (B_ * S_) / 128, 3), blk, SM_BNT>>>(
        P0, P1, P2, nullptr, nullptr, H_, H_, H_, 0, 0, 0, 0, 1.0f);

    // energy + exp (unnormalized) + row partial sums, n-walk of 8 tiles,
    // j-pipelined epilogue
    energy_tc<<<dim3(S_ / (128 * NWALK), S_ / 128, B_ * NH_), blk, SM_EN>>>(
        Qp, Kp, attn, Pp);

    // ctx = softmax(attn) @ V; writes normalized attention back in place
    avk<<<dim3(1, S_ / 128, B_ * NH_), blk, SM_AV>>>(
        PA, PN, PN, Pp, attn, S_, S_, HD_, 0,
        (long)S_ * S_, (long)S_ * HD_, 0, 1.0f);

    // x = ctx @ Wo^T + bo -> d_out (NT)
    oprj<<<dim3(H_ / 128, (B_ * S_) / 128, 1), blk, SM_BNT>>>(
        PO, PN, PN, nullptr, nullptr, H_, H_, H_, H_, 0, 0, 0, 1.0f);
}

// round 15
// speedup vs baseline: 2.8735x; 1.0012x over previous
#include <cuda_runtime.h>
#include <cstdint>

// Problem constants
#define B_  2
#define S_  4096
#define H_  512
#define NH_ 8
#define HD_ 64
#define XSZ (B_ * S_ * H_)                       // 4,194,304 floats (x output)
#define ASZ ((long)B_ * NH_ * S_ * S_)           // 268,435,456 floats (attention)
#define GXE (S_ / 128)                           // energy col-tiles per row = 32
#define NWALK 8                                  // n-tiles walked per energy CTA

// Scratch (device globals: the sanctioned allocation-free workaround)
__device__ float g_Q[B_ * NH_ * S_ * HD_];        // tf32-rounded
__device__ float g_K[B_ * NH_ * S_ * HD_];        // tf32-rounded
__device__ float g_V[B_ * NH_ * S_ * HD_];        // tf32-rounded
__device__ float g_ctx[B_ * S_ * H_];             // tf32-rounded
__device__ float g_psum[(long)B_ * NH_ * S_ * GXE];
__device__ float g_attn_fb[(long)B_ * NH_ * S_ * S_];

struct PtrSet { const float* A; const float* B; const float* bias; float* C; };

// ---- helpers ----------------------------------------------------------------
__device__ __forceinline__ float f2tf32(float f) {
    unsigned u;
    asm("cvt.rna.tf32.f32 %0, %1;" : "=r"(u) : "f"(f));
    return __uint_as_float(u);
}
template<bool CVT>
__device__ __forceinline__ unsigned frag(float f) {
    if (CVT) { unsigned u; asm("cvt.rna.tf32.f32 %0, %1;" : "=r"(u) : "f"(f)); return u; }
    return __float_as_uint(f);
}
__device__ __forceinline__ void mma_tf32(float* c, const unsigned* a, const unsigned* b) {
    asm volatile(
        "mma.sync.aligned.m16n8k8.row.col.f32.tf32.tf32.f32 "
        "{%0,%1,%2,%3}, {%4,%5,%6,%7}, {%8,%9}, {%0,%1,%2,%3};"
        : "+f"(c[0]), "+f"(c[1]), "+f"(c[2]), "+f"(c[3])
        : "r"(a[0]), "r"(a[1]), "r"(a[2]), "r"(a[3]), "r"(b[0]), "r"(b[1]));
}
__device__ __forceinline__ unsigned sptr(const void* p) {
    return (unsigned)__cvta_generic_to_shared(p);
}
__device__ __forceinline__ void cp16(unsigned d, const void* s) {
    asm volatile("cp.async.cg.shared.global [%0], [%1], 16;" :: "r"(d), "l"(s));
}
__device__ __forceinline__ void cpcommit() { asm volatile("cp.async.commit_group;"); }
template<int N> __device__ __forceinline__ void cpwait() {
    asm volatile("cp.async.wait_group %0;" :: "n"(N));
}

// ---------------------------------------------------------------------------
// Energy kernel, n-walk + j-pipelined version.
// Each CTA: one 128-row Q tile, fragments hoisted to REGISTERS once (64 regs),
// then a walk over NWALK 128-col K tiles (double-buffered cp.async).
// Per tile, the 8 n-subtiles are software-pipelined: MMA(j) issues, then the
// epilogue (exp + STG + rowsum) of subtile j-1 runs while the tensor pipe
// drains -> MUFU/STG overlap HMMA instead of serializing after it.
// attn = exp((Q @ K^T)/8) (unnormalized); deterministic per-row partial sums
// psum[(z*S+row)*GXE + (bx*NWALK+nt)].
// ---------------------------------------------------------------------------
__global__ void __launch_bounds__(256, 2) energy_tc(
    const float* __restrict__ Q, const float* __restrict__ Km,
    float* __restrict__ attn, float* __restrict__ psum)
{
    constexpr int LDE = 68;                      // row stride (floats)
    extern __shared__ float sm[];
    float* Qs = sm;                              // [128][LDE] (used once)
    float* Ks = sm + 128 * LDE;                  // [2][128][LDE]
    __shared__ float rsum[128][2];

    const int z = blockIdx.z;
    Q    += (long)z * S_ * HD_;
    Km   += (long)z * S_ * HD_;
    attn += (long)z * S_ * S_;

    const int m0     = blockIdx.y * 128;
    const int n_base = blockIdx.x * (128 * NWALK);
    const int t = threadIdx.x, warp = t >> 5, lane = t & 31;
    const int wm = warp >> 1, wn = warp & 1;
    const int lr = lane >> 2, lc = lane & 3;

    const int fr = t >> 1;                       // fill row (0..127)
    const int fc = (t & 1) * 8;                  // fill chunk base (float4 units)

    auto fillK = [&](int buf, int n0) {
        unsigned db = sptr(Ks + (buf * 128 + fr) * LDE + fc * 4);
        const float* gb = Km + (long)(n0 + fr) * HD_ + fc * 4;
        #pragma unroll
        for (int j = 0; j < 8; ++j) cp16(db + j * 16, gb + j * 4);
    };

    // Q fill (once) + K tile 0, one commit group
    {
        unsigned da = sptr(Qs + fr * LDE + fc * 4);
        const float* ga = Q + (long)(m0 + fr) * HD_ + fc * 4;
        #pragma unroll
        for (int j = 0; j < 8; ++j) cp16(da + j * 16, ga + j * 4);
    }
    fillK(0, n_base);
    cpcommit();
    cpwait<0>();
    __syncthreads();

    // ---- hoist Q fragments to registers (once per CTA) ----
    unsigned qa[8][2][4];
    #pragma unroll
    for (int ks = 0; ks < 8; ++ks) {
        const int kc = ks * 8 + lc;
        #pragma unroll
        for (int i = 0; i < 2; ++i) {
            const float* qp = Qs + (wm * 32 + i * 16 + lr) * LDE;
            qa[ks][i][0] = __float_as_uint(qp[kc              ]);
            qa[ks][i][1] = __float_as_uint(qp[8 * LDE + kc    ]);
            qa[ks][i][2] = __float_as_uint(qp[kc + 4          ]);
            qa[ks][i][3] = __float_as_uint(qp[8 * LDE + kc + 4]);
        }
    }

    for (int nt = 0; nt < NWALK; ++nt) {
        const int cur = nt & 1;
        if (nt + 1 < NWALK) {
            fillK(cur ^ 1, n_base + (nt + 1) * 128);
            cpcommit();
            cpwait<1>();
        } else {
            cpwait<0>();
        }
        __syncthreads();

        const int n0 = n_base + nt * 128;
        float sum[2][2] = {};                    // [i][rows lr / lr+8]
        float acc[2][2][4];                      // [j&1][i][4]

        // epilogue of subtile jj (acc slot jb): exp, STG, rowsum accumulate
        auto epi = [&](int jj, int jb) {
            const int cc = n0 + wn * 64 + jj * 8 + 2 * lc;
            #pragma unroll
            for (int i = 0; i < 2; ++i) {
                const int rr = m0 + wm * 32 + i * 16 + lr;
                float e0 = __expf(acc[jb][i][0] * 0.125f);
                float e1 = __expf(acc[jb][i][1] * 0.125f);
                float e2 = __expf(acc[jb][i][2] * 0.125f);
                float e3 = __expf(acc[jb][i][3] * 0.125f);
                sum[i][0] += e0 + e1;
                sum[i][1] += e2 + e3;
                *(float2*)(attn + (long)rr * S_ + cc)       = make_float2(e0, e1);
                *(float2*)(attn + (long)(rr + 8) * S_ + cc) = make_float2(e2, e3);
            }
        };

        // ---- j-pipelined MMA: issue MMAs of j, then drain epilogue of j-1 ----
        #pragma unroll
        for (int j = 0; j < 8; ++j) {
            const int jb = j & 1;
            #pragma unroll
            for (int i = 0; i < 2; ++i)
                #pragma unroll
                for (int q = 0; q < 4; ++q) acc[jb][i][q] = 0.0f;

            const float* kp = Ks + (cur * 128 + wn * 64 + j * 8 + lr) * LDE;
            #pragma unroll
            for (int ks = 0; ks < 8; ++ks) {
                const int kc = ks * 8 + lc;
                unsigned b[2] = { __float_as_uint(kp[kc    ]),
                                  __float_as_uint(kp[kc + 4]) };
                mma_tf32(acc[jb][0], qa[ks][0], b);
                mma_tf32(acc[jb][1], qa[ks][1], b);
            }
            if (j > 0) epi(j - 1, jb ^ 1);
        }
        epi(7, 1);

        // ---- row-sum reduce (4 lanes share each row) ----
        #pragma unroll
        for (int i = 0; i < 2; ++i) {
            float s0 = sum[i][0], s1 = sum[i][1];
            s0 += __shfl_xor_sync(0xffffffffu, s0, 1);
            s0 += __shfl_xor_sync(0xffffffffu, s0, 2);
            s1 += __shfl_xor_sync(0xffffffffu, s1, 1);
            s1 += __shfl_xor_sync(0xffffffffu, s1, 2);
            if (lc == 0) {
                rsum[wm * 32 + i * 16 + lr    ][wn] = s0;
                rsum[wm * 32 + i * 16 + 8 + lr][wn] = s1;
            }
        }
        // barrier: rsum complete; also guarantees all MMA reads of Ks[cur]
        // are done before the next iteration's fillK overwrites the peer buf.
        __syncthreads();
        if (t < 128)
            psum[((long)z * S_ + m0 + t) * GXE + blockIdx.x * NWALK + nt] =
                rsum[t][0] + rsum[t][1];
    }
}

// ---------------------------------------------------------------------------
// Double-buffered tf32 GEMM (cp.async pipeline): C = scale*(A x B) + bias
//   TM x TN tile, BK=32, 256 threads, warp tile WM x WN, m16n8k8.
//   BNT ? B[N,K] (NT, smem [n][k] stride 36) : B[K,N] (NN, smem [k][n] stride TN+8).
//   CVTA/CVTB: RNA-round fragments post-LDS (for raw-fp32 operands).
//   OUTMODE 0: row-major; 1: head-split [B,NH,S,HD]; 2: per-head AV merged
//   into [B,S,H]. OUTMODE!=0 tf32-rounds stores (consumed by later MMAs).
//   NORM: A is unnormalized exp; prologue builds inv row sums from psum;
//   staged A tiles are written back normalized (final attention) and the
//   accumulator is normalized in the epilogue.
//   MERGE3: z in {0,1,2} selects pointer set p0/p1/p2 (independent GEMMs in
//   one launch); otherwise z applies the sAz/sBz/sCz batch offsets to p0.
// ---------------------------------------------------------------------------
template<int TM, int TN, int WM, int WN, bool BNT, int OUTMODE, bool NORM,
         bool CVTA, bool CVTB, bool MERGE3>
__global__ void __launch_bounds__(256, 2) gemm_db(
    PtrSet p0, PtrSet p1, PtrSet p2,
    const float* __restrict__ psum, float* __restrict__ Aw,
    int K, int lda, int ldb, int ldc,
    long sAz, long sBz, long sCz, float scale)
{
    constexpr int BK   = 32;
    constexpr int LA   = 36;
    constexpr int LB   = BNT ? 36 : TN + 8;
    constexpr int ABUF = TM * LA;
    constexpr int BBUF = BNT ? TN * LB : BK * LB;
    constexpr int WGN  = TN / WN;
    constexpr int MT   = WM / 16;
    constexpr int NT   = WN / 8;
    static_assert((TM / WM) * WGN == 8, "warp grid must be 8 warps");

    extern __shared__ float sm[];
    float* As = sm;                    // [2][TM][LA]
    float* Bs = sm + 2 * ABUF;         // [2][...]
    __shared__ float inv_s[NORM ? TM : 1];

    const int z = blockIdx.z;
    PtrSet P = p0;
    if (MERGE3) { if (z == 1) P = p1; else if (z == 2) P = p2; }
    const float* A  = P.A;
    const float* Bm = P.B;
    const float* bias = P.bias;
    float* C = P.C;
    if (!MERGE3) {
        A  += (long)z * sAz;
        Bm += (long)z * sBz;
        C  += (long)z * sCz;
        if (NORM) Aw += (long)z * sAz;
    }

    const int m0 = blockIdx.y * TM;
    const int n0 = blockIdx.x * TN;
    const int t = threadIdx.x, warp = t >> 5, lane = t & 31;
    const int wm = warp / WGN, wn = warp % WGN;
    const int lr = lane >> 2, lc = lane & 3;

    if (NORM) {
        if (t < TM) {
            const float4* pp = (const float4*)(psum + ((long)z * S_ + m0 + t) * GXE);
            float s = 0.0f;
            #pragma unroll
            for (int q = 0; q < GXE / 4; ++q) {
                float4 v = pp[q];
                s += (v.x + v.y) + (v.z + v.w);
            }
            inv_s[t] = 1.0f / s;
        }
        __syncthreads();
    }

    auto fill = [&](int buf, int k0) {
        #pragma unroll
        for (int s = 0; s < TM * BK / 1024; ++s) {        // A tile
            const int idx = t + 256 * s;
            const int r = idx >> 3, c4 = idx & 7;
            cp16(sptr(As + buf * ABUF + r * LA + c4 * 4),
                 A + (long)(m0 + r) * lda + k0 + c4 * 4);
        }
        if (BNT) {
            #pragma unroll
            for (int s = 0; s < TN * BK / 1024; ++s) {
                const int idx = t + 256 * s;
                const int r = idx >> 3, c4 = idx & 7;
                cp16(sptr(Bs + buf * BBUF + r * LB + c4 * 4),
                     Bm + (long)(n0 + r) * ldb + k0 + c4 * 4);
            }
        } else {
            #pragma unroll
            for (int s = 0; s < BK * TN / 1024; ++s) {
                const int idx = t + 256 * s;
                const int kr = idx / (TN / 4), c4 = idx % (TN / 4);
                cp16(sptr(Bs + buf * BBUF + kr * LB + c4 * 4),
                     Bm + (long)(k0 + kr) * ldb + n0 + c4 * 4);
            }
        }
    };

    float acc[MT][NT][4] = {};
    const int NIT = K / BK;

    fill(0, 0);
    cpcommit();

    for (int it = 0; it < NIT; ++it) {
        const int cur = it & 1;
        if (it + 1 < NIT) {
            fill(cur ^ 1, (it + 1) * BK);
            cpcommit();
            cpwait<1>();
        } else {
            cpwait<0>();
        }
        __syncthreads();

        if (NORM) {
            // mandatory normalized-attention write, streamed from smem
            #pragma unroll
            for (int s = 0; s < TM * BK / 1024; ++s) {
                const int idx = t + 256 * s;
                const int r = idx >> 3, c4 = idx & 7;
                float4 v = *(const float4*)(As + cur * ABUF + r * LA + c4 * 4);
                const float iv = inv_s[r];
                v.x *= iv; v.y *= iv; v.z *= iv; v.w *= iv;
                *(float4*)(Aw + (long)(m0 + r) * lda + it * BK + c4 * 4) = v;
            }
        }

        #pragma unroll
        for (int ks = 0; ks < BK / 8; ++ks) {
            const int kc = ks * 8 + lc;
            unsigned a[MT][4], b[NT][2];
            #pragma unroll
            for (int i = 0; i < MT; ++i) {
                const float* ap = As + cur * ABUF;
                const int row = wm * WM + i * 16 + lr;
                a[i][0] = frag<CVTA>(ap[(row    ) * LA + kc    ]);
                a[i][1] = frag<CVTA>(ap[(row + 8) * LA + kc    ]);
                a[i][2] = frag<CVTA>(ap[(row    ) * LA + kc + 4]);
                a[i][3] = frag<CVTA>(ap[(row + 8) * LA + kc + 4]);
            }
            #pragma unroll
            for (int j = 0; j < NT; ++j) {
                const float* bp = Bs + cur * BBUF;
                const int col = wn * WN + j * 8 + lr;
                if (BNT) {
                    b[j][0] = frag<CVTB>(bp[col * LB + kc    ]);
                    b[j][1] = frag<CVTB>(bp[col * LB + kc + 4]);
                } else {
                    b[j][0] = frag<CVTB>(bp[(kc    ) * LB + col]);
                    b[j][1] = frag<CVTB>(bp[(kc + 4) * LB + col]);
                }
            }
            #pragma unroll
            for (int i = 0; i < MT; ++i)
                #pragma unroll
                for (int j = 0; j < NT; ++j)
                    mma_tf32(acc[i][j], a[i], b[j]);
        }
        __syncthreads();
    }

    // ---- epilogue ----
    #pragma unroll
    for (int i = 0; i < MT; ++i) {
        const int rloc = wm * WM + i * 16 + lr;
        const float iv0 = NORM ? inv_s[rloc]     : 1.0f;
        const float iv1 = NORM ? inv_s[rloc + 8] : 1.0f;
        #pragma unroll
        for (int j = 0; j < NT; ++j) {
            const int rr = m0 + rloc;
            const int cc = n0 + wn * WN + j * 8 + 2 * lc;
            const float b0 = bias ? bias[cc] : 0.0f;
            const float b1 = bias ? bias[cc + 1] : 0.0f;
            float2 v0 = make_float2(acc[i][j][0] * scale * iv0 + b0,
                                    acc[i][j][1] * scale * iv0 + b1);
            float2 v1 = make_float2(acc[i][j][2] * scale * iv1 + b0,
                                    acc[i][j][3] * scale * iv1 + b1);
            if (OUTMODE != 0) {   // scratch consumed by tf32 MMAs: pre-round
                v0.x = f2tf32(v0.x); v0.y = f2tf32(v0.y);
                v1.x = f2tf32(v1.x); v1.y = f2tf32(v1.y);
            }
            #pragma unroll
            for (int h = 0; h < 2; ++h) {
                const int m = rr + h * 8;
                const float2 v = h ? v1 : v0;
                float* dst;
                if (OUTMODE == 1) {
                    const int bb = m / S_, ss = m % S_;
                    const int hh = cc / HD_, dd = cc % HD_;
                    dst = C + (((long)(bb * NH_ + hh) * S_ + ss) * HD_ + dd);
                } else if (OUTMODE == 2) {
                    dst = C + ((long)(z >> 3) * ((long)S_ * H_)
                              + (long)(z & 7) * HD_ + (long)m * H_ + cc);
                } else {
                    dst = C + ((long)m * ldc + cc);
                }
                *(float2*)dst = v;
            }
        }
    }
}

// ---------------------------------------------------------------------------
// kernel_launch
// Inputs: query, key, value, Wq, bq, Wk, bk, Wv, bv, Wo, bo
// Output: [ x (B*S*H) | attention (B*NH*S*S) ]
// ---------------------------------------------------------------------------
extern "C" void kernel_launch(void* const* d_in, const int* in_sizes, int n_in,
                              void* d_out, int out_size)
{
    const float* query = (const float*)d_in[0];
    const float* key_  = (const float*)d_in[1];
    const float* value = (const float*)d_in[2];
    const float* Wq = (const float*)d_in[3];
    const float* bq = (const float*)d_in[4];
    const float* Wk = (const float*)d_in[5];
    const float* bk = (const float*)d_in[6];
    const float* Wv = (const float*)d_in[7];
    const float* bv = (const float*)d_in[8];
    const float* Wo = (const float*)d_in[9];
    const float* bo = (const float*)d_in[10];

    float* xout = (float*)d_out;

    float *Qp, *Kp, *Vp, *Cp, *Pp, *Afb;
    cudaGetSymbolAddress((void**)&Qp, g_Q);
    cudaGetSymbolAddress((void**)&Kp, g_K);
    cudaGetSymbolAddress((void**)&Vp, g_V);
    cudaGetSymbolAddress((void**)&Cp, g_ctx);
    cudaGetSymbolAddress((void**)&Pp, g_psum);
    cudaGetSymbolAddress((void**)&Afb, g_attn_fb);

    float* attn = ((long)out_size >= (long)XSZ + ASZ) ? (xout + XSZ) : Afb;

    // dynamic smem sizes
    const int SM_BNT = 2 * (128 * 36 + 128 * 36) * 4;          // 73728
    const int SM_AV  = (2 * 128 * 36 + 2 * 32 * 72) * 4;       // 55296
    const int SM_EN  = (128 + 256) * 68 * 4;                   // 104448

    auto proj = gemm_db<128, 128, 32, 64, true, 1, false, true, true, true>;
    auto oprj = gemm_db<128, 128, 32, 64, true, 0, false, false, true, false>;
    auto avk  = gemm_db<128,  64, 32, 32, false, 2, true, true, false, false>;

    cudaFuncSetAttribute(proj, cudaFuncAttributeMaxDynamicSharedMemorySize, SM_BNT);
    cudaFuncSetAttribute(oprj, cudaFuncAttributeMaxDynamicSharedMemorySize, SM_BNT);
    cudaFuncSetAttribute(avk,  cudaFuncAttributeMaxDynamicSharedMemorySize, SM_AV);
    cudaFuncSetAttribute(energy_tc, cudaFuncAttributeMaxDynamicSharedMemorySize, SM_EN);

    const dim3 blk(256);
    const PtrSet P0{query, Wq, bq, Qp};
    const PtrSet P1{key_,  Wk, bk, Kp};
    const PtrSet P2{value, Wv, bv, Vp};
    const PtrSet PO{Cp,    Wo, bo, xout};
    const PtrSet PA{attn,  Vp, nullptr, Cp};
    const PtrSet PN{nullptr, nullptr, nullptr, nullptr};

    // Q/K/V projections merged into ONE launch (z selects the pointer set)
    proj<<<dim3(H_ / 128, (B_ * S_) / 128, 3), blk, SM_BNT>>>(
        P0, P1, P2, nullptr, nullptr, H_, H_, H_, 0, 0, 0, 0, 1.0f);

    // energy + exp (unnormalized) + row partial sums, n-walk of 8 tiles,
    // j-pipelined epilogue
    energy_tc<<<dim3(S_ / (128 * NWALK), S_ / 128, B_ * NH_), blk, SM_EN>>>(
        Qp, Kp, attn, Pp);

    // ctx = softmax(attn) @ V; writes normalized attention back in place
    avk<<<dim3(1, S_ / 128, B_ * NH_), blk, SM_AV>>>(
        PA, PN, PN, Pp, attn, S_, S_, HD_, 0,
        (long)S_ * S_, (long)S_ * HD_, 0, 1.0f);

    // x = ctx @ Wo^T + bo -> d_out (NT)
    oprj<<<dim3(H_ / 128, (B_ * S_) / 128, 1), blk, SM_BNT>>>(
        PO, PN, PN, nullptr, nullptr, H_, H_, H_, H_, 0, 0, 0, 1.0f);
}

// round 16
// speedup vs baseline: 2.8769x; 1.0012x over previous
#include <cuda_runtime.h>
#include <cstdint>

// Problem constants
#define B_  2
#define S_  4096
#define H_  512
#define NH_ 8
#define HD_ 64
#define XSZ (B_ * S_ * H_)                       // 4,194,304 floats (x output)
#define ASZ ((long)B_ * NH_ * S_ * S_)           // 268,435,456 floats (attention)
#define GXE (S_ / 128)                           // energy col-tiles per row = 32
#define NWALK 8                                  // n-tiles walked per energy CTA

// Scratch (device globals: the sanctioned allocation-free workaround)
__device__ float g_Q[B_ * NH_ * S_ * HD_];        // tf32-rounded
__device__ float g_K[B_ * NH_ * S_ * HD_];        // tf32-rounded
__device__ float g_V[B_ * NH_ * S_ * HD_];        // tf32-rounded
__device__ float g_ctx[B_ * S_ * H_];             // tf32-rounded
__device__ float g_psum[(long)B_ * NH_ * S_ * GXE];
__device__ float g_attn_fb[(long)B_ * NH_ * S_ * S_];

struct PtrSet { const float* A; const float* B; const float* bias; float* C; };

// ---- helpers ----------------------------------------------------------------
__device__ __forceinline__ float f2tf32(float f) {
    unsigned u;
    asm("cvt.rna.tf32.f32 %0, %1;" : "=r"(u) : "f"(f));
    return __uint_as_float(u);
}
template<bool CVT>
__device__ __forceinline__ unsigned frag(float f) {
    if (CVT) { unsigned u; asm("cvt.rna.tf32.f32 %0, %1;" : "=r"(u) : "f"(f)); return u; }
    return __float_as_uint(f);
}
__device__ __forceinline__ void mma_tf32(float* c, const unsigned* a, const unsigned* b) {
    asm volatile(
        "mma.sync.aligned.m16n8k8.row.col.f32.tf32.tf32.f32 "
        "{%0,%1,%2,%3}, {%4,%5,%6,%7}, {%8,%9}, {%0,%1,%2,%3};"
        : "+f"(c[0]), "+f"(c[1]), "+f"(c[2]), "+f"(c[3])
        : "r"(a[0]), "r"(a[1]), "r"(a[2]), "r"(a[3]), "r"(b[0]), "r"(b[1]));
}
__device__ __forceinline__ unsigned sptr(const void* p) {
    return (unsigned)__cvta_generic_to_shared(p);
}
__device__ __forceinline__ void cp16(unsigned d, const void* s) {
    asm volatile("cp.async.cg.shared.global [%0], [%1], 16;" :: "r"(d), "l"(s));
}
__device__ __forceinline__ void cpcommit() { asm volatile("cp.async.commit_group;"); }
template<int N> __device__ __forceinline__ void cpwait() {
    asm volatile("cp.async.wait_group %0;" :: "n"(N));
}

// ---------------------------------------------------------------------------
// Energy kernel, n-walk + j-pipelined version.
// Each CTA: one 128-row Q tile, fragments hoisted to REGISTERS once (64 regs),
// then a walk over NWALK 128-col K tiles (double-buffered cp.async).
// Per tile, the 8 n-subtiles are software-pipelined: MMA(j) issues, then the
// epilogue (exp + STG + rowsum) of subtile j-1 runs while the tensor pipe
// drains -> MUFU/STG overlap HMMA instead of serializing after it.
// attn = exp((Q @ K^T)/8) (unnormalized); deterministic per-row partial sums
// psum[(z*S+row)*GXE + (bx*NWALK+nt)].
// ---------------------------------------------------------------------------
__global__ void __launch_bounds__(256, 2) energy_tc(
    const float* __restrict__ Q, const float* __restrict__ Km,
    float* __restrict__ attn, float* __restrict__ psum)
{
    constexpr int LDE = 68;                      // row stride (floats)
    extern __shared__ float sm[];
    float* Qs = sm;                              // [128][LDE] (used once)
    float* Ks = sm + 128 * LDE;                  // [2][128][LDE]
    __shared__ float rsum[128][2];

    const int z = blockIdx.z;
    Q    += (long)z * S_ * HD_;
    Km   += (long)z * S_ * HD_;
    attn += (long)z * S_ * S_;

    const int m0     = blockIdx.y * 128;
    const int n_base = blockIdx.x * (128 * NWALK);
    const int t = threadIdx.x, warp = t >> 5, lane = t & 31;
    const int wm = warp >> 1, wn = warp & 1;
    const int lr = lane >> 2, lc = lane & 3;

    const int fr = t >> 1;                       // fill row (0..127)
    const int fc = (t & 1) * 8;                  // fill chunk base (float4 units)

    auto fillK = [&](int buf, int n0) {
        unsigned db = sptr(Ks + (buf * 128 + fr) * LDE + fc * 4);
        const float* gb = Km + (long)(n0 + fr) * HD_ + fc * 4;
        #pragma unroll
        for (int j = 0; j < 8; ++j) cp16(db + j * 16, gb + j * 4);
    };

    // Q fill (once) + K tile 0, one commit group
    {
        unsigned da = sptr(Qs + fr * LDE + fc * 4);
        const float* ga = Q + (long)(m0 + fr) * HD_ + fc * 4;
        #pragma unroll
        for (int j = 0; j < 8; ++j) cp16(da + j * 16, ga + j * 4);
    }
    fillK(0, n_base);
    cpcommit();
    cpwait<0>();
    __syncthreads();

    // ---- hoist Q fragments to registers (once per CTA) ----
    unsigned qa[8][2][4];
    #pragma unroll
    for (int ks = 0; ks < 8; ++ks) {
        const int kc = ks * 8 + lc;
        #pragma unroll
        for (int i = 0; i < 2; ++i) {
            const float* qp = Qs + (wm * 32 + i * 16 + lr) * LDE;
            qa[ks][i][0] = __float_as_uint(qp[kc              ]);
            qa[ks][i][1] = __float_as_uint(qp[8 * LDE + kc    ]);
            qa[ks][i][2] = __float_as_uint(qp[kc + 4          ]);
            qa[ks][i][3] = __float_as_uint(qp[8 * LDE + kc + 4]);
        }
    }

    for (int nt = 0; nt < NWALK; ++nt) {
        const int cur = nt & 1;
        if (nt + 1 < NWALK) {
            fillK(cur ^ 1, n_base + (nt + 1) * 128);
            cpcommit();
            cpwait<1>();
        } else {
            cpwait<0>();
        }
        __syncthreads();

        const int n0 = n_base + nt * 128;
        float sum[2][2] = {};                    // [i][rows lr / lr+8]
        float acc[2][2][4];                      // [j&1][i][4]

        // epilogue of subtile jj (acc slot jb): exp, STG, rowsum accumulate
        auto epi = [&](int jj, int jb) {
            const int cc = n0 + wn * 64 + jj * 8 + 2 * lc;
            #pragma unroll
            for (int i = 0; i < 2; ++i) {
                const int rr = m0 + wm * 32 + i * 16 + lr;
                float e0 = __expf(acc[jb][i][0] * 0.125f);
                float e1 = __expf(acc[jb][i][1] * 0.125f);
                float e2 = __expf(acc[jb][i][2] * 0.125f);
                float e3 = __expf(acc[jb][i][3] * 0.125f);
                sum[i][0] += e0 + e1;
                sum[i][1] += e2 + e3;
                *(float2*)(attn + (long)rr * S_ + cc)       = make_float2(e0, e1);
                *(float2*)(attn + (long)(rr + 8) * S_ + cc) = make_float2(e2, e3);
            }
        };

        // ---- j-pipelined MMA: issue MMAs of j, then drain epilogue of j-1 ----
        #pragma unroll
        for (int j = 0; j < 8; ++j) {
            const int jb = j & 1;
            #pragma unroll
            for (int i = 0; i < 2; ++i)
                #pragma unroll
                for (int q = 0; q < 4; ++q) acc[jb][i][q] = 0.0f;

            const float* kp = Ks + (cur * 128 + wn * 64 + j * 8 + lr) * LDE;
            #pragma unroll
            for (int ks = 0; ks < 8; ++ks) {
                const int kc = ks * 8 + lc;
                unsigned b[2] = { __float_as_uint(kp[kc    ]),
                                  __float_as_uint(kp[kc + 4]) };
                mma_tf32(acc[jb][0], qa[ks][0], b);
                mma_tf32(acc[jb][1], qa[ks][1], b);
            }
            if (j > 0) epi(j - 1, jb ^ 1);
        }
        epi(7, 1);

        // ---- row-sum reduce (4 lanes share each row) ----
        #pragma unroll
        for (int i = 0; i < 2; ++i) {
            float s0 = sum[i][0], s1 = sum[i][1];
            s0 += __shfl_xor_sync(0xffffffffu, s0, 1);
            s0 += __shfl_xor_sync(0xffffffffu, s0, 2);
            s1 += __shfl_xor_sync(0xffffffffu, s1, 1);
            s1 += __shfl_xor_sync(0xffffffffu, s1, 2);
            if (lc == 0) {
                rsum[wm * 32 + i * 16 + lr    ][wn] = s0;
                rsum[wm * 32 + i * 16 + 8 + lr][wn] = s1;
            }
        }
        // barrier: rsum complete; also guarantees all MMA reads of Ks[cur]
        // are done before the next iteration's fillK overwrites the peer buf.
        __syncthreads();
        if (t < 128)
            psum[((long)z * S_ + m0 + t) * GXE + blockIdx.x * NWALK + nt] =
                rsum[t][0] + rsum[t][1];
    }
}

// ---------------------------------------------------------------------------
// Double-buffered tf32 GEMM (cp.async pipeline): C = scale*(A x B) + bias
//   TM x TN tile, BK=32, 256 threads, warp tile WM x WN, m16n8k8.
//   BNT ? B[N,K] (NT, smem [n][k] stride 36) : B[K,N] (NN, smem [k][n] stride TN+8).
//   CVTA/CVTB: RNA-round fragments post-LDS (for raw-fp32 operands).
//   OUTMODE 0: row-major; 1: head-split [B,NH,S,HD]; 2: per-head AV merged
//   into [B,S,H]. OUTMODE!=0 tf32-rounds stores (consumed by later MMAs).
//   NORM: A is unnormalized exp; prologue builds inv row sums from psum;
//   staged A tiles are written back normalized (final attention) and the
//   accumulator is normalized in the epilogue.
//   MERGE3: z in {0,1,2} selects pointer set p0/p1/p2 (independent GEMMs in
//   one launch); otherwise z applies the sAz/sBz/sCz batch offsets to p0.
// ---------------------------------------------------------------------------
template<int TM, int TN, int WM, int WN, bool BNT, int OUTMODE, bool NORM,
         bool CVTA, bool CVTB, bool MERGE3>
__global__ void __launch_bounds__(256, 2) gemm_db(
    PtrSet p0, PtrSet p1, PtrSet p2,
    const float* __restrict__ psum, float* __restrict__ Aw,
    int K, int lda, int ldb, int ldc,
    long sAz, long sBz, long sCz, float scale)
{
    constexpr int BK   = 32;
    constexpr int LA   = 36;
    constexpr int LB   = BNT ? 36 : TN + 8;
    constexpr int ABUF = TM * LA;
    constexpr int BBUF = BNT ? TN * LB : BK * LB;
    constexpr int WGN  = TN / WN;
    constexpr int MT   = WM / 16;
    constexpr int NT   = WN / 8;
    static_assert((TM / WM) * WGN == 8, "warp grid must be 8 warps");

    extern __shared__ float sm[];
    float* As = sm;                    // [2][TM][LA]
    float* Bs = sm + 2 * ABUF;         // [2][...]
    __shared__ float inv_s[NORM ? TM : 1];

    const int z = blockIdx.z;
    PtrSet P = p0;
    if (MERGE3) { if (z == 1) P = p1; else if (z == 2) P = p2; }
    const float* A  = P.A;
    const float* Bm = P.B;
    const float* bias = P.bias;
    float* C = P.C;
    if (!MERGE3) {
        A  += (long)z * sAz;
        Bm += (long)z * sBz;
        C  += (long)z * sCz;
        if (NORM) Aw += (long)z * sAz;
    }

    const int m0 = blockIdx.y * TM;
    const int n0 = blockIdx.x * TN;
    const int t = threadIdx.x, warp = t >> 5, lane = t & 31;
    const int wm = warp / WGN, wn = warp % WGN;
    const int lr = lane >> 2, lc = lane & 3;

    if (NORM) {
        if (t < TM) {
            const float4* pp = (const float4*)(psum + ((long)z * S_ + m0 + t) * GXE);
            float s = 0.0f;
            #pragma unroll
            for (int q = 0; q < GXE / 4; ++q) {
                float4 v = pp[q];
                s += (v.x + v.y) + (v.z + v.w);
            }
            inv_s[t] = 1.0f / s;
        }
        __syncthreads();
    }

    auto fill = [&](int buf, int k0) {
        #pragma unroll
        for (int s = 0; s < TM * BK / 1024; ++s) {        // A tile
            const int idx = t + 256 * s;
            const int r = idx >> 3, c4 = idx & 7;
            cp16(sptr(As + buf * ABUF + r * LA + c4 * 4),
                 A + (long)(m0 + r) * lda + k0 + c4 * 4);
        }
        if (BNT) {
            #pragma unroll
            for (int s = 0; s < TN * BK / 1024; ++s) {
                const int idx = t + 256 * s;
                const int r = idx >> 3, c4 = idx & 7;
                cp16(sptr(Bs + buf * BBUF + r * LB + c4 * 4),
                     Bm + (long)(n0 + r) * ldb + k0 + c4 * 4);
            }
        } else {
            #pragma unroll
            for (int s = 0; s < BK * TN / 1024; ++s) {
                const int idx = t + 256 * s;
                const int kr = idx / (TN / 4), c4 = idx % (TN / 4);
                cp16(sptr(Bs + buf * BBUF + kr * LB + c4 * 4),
                     Bm + (long)(k0 + kr) * ldb + n0 + c4 * 4);
            }
        }
    };

    float acc[MT][NT][4] = {};
    const int NIT = K / BK;

    fill(0, 0);
    cpcommit();

    for (int it = 0; it < NIT; ++it) {
        const int cur = it & 1;
        if (it + 1 < NIT) {
            fill(cur ^ 1, (it + 1) * BK);
            cpcommit();
            cpwait<1>();
        } else {
            cpwait<0>();
        }
        __syncthreads();

        if (NORM) {
            // mandatory normalized-attention write, streamed from smem
            #pragma unroll
            for (int s = 0; s < TM * BK / 1024; ++s) {
                const int idx = t + 256 * s;
                const int r = idx >> 3, c4 = idx & 7;
                float4 v = *(const float4*)(As + cur * ABUF + r * LA + c4 * 4);
                const float iv = inv_s[r];
                v.x *= iv; v.y *= iv; v.z *= iv; v.w *= iv;
                *(float4*)(Aw + (long)(m0 + r) * lda + it * BK + c4 * 4) = v;
            }
        }

        #pragma unroll
        for (int ks = 0; ks < BK / 8; ++ks) {
            const int kc = ks * 8 + lc;
            unsigned a[MT][4], b[NT][2];
            #pragma unroll
            for (int i = 0; i < MT; ++i) {
                const float* ap = As + cur * ABUF;
                const int row = wm * WM + i * 16 + lr;
                a[i][0] = frag<CVTA>(ap[(row    ) * LA + kc    ]);
                a[i][1] = frag<CVTA>(ap[(row + 8) * LA + kc    ]);
                a[i][2] = frag<CVTA>(ap[(row    ) * LA + kc + 4]);
                a[i][3] = frag<CVTA>(ap[(row + 8) * LA + kc + 4]);
            }
            #pragma unroll
            for (int j = 0; j < NT; ++j) {
                const float* bp = Bs + cur * BBUF;
                const int col = wn * WN + j * 8 + lr;
                if (BNT) {
                    b[j][0] = frag<CVTB>(bp[col * LB + kc    ]);
                    b[j][1] = frag<CVTB>(bp[col * LB + kc + 4]);
                } else {
                    b[j][0] = frag<CVTB>(bp[(kc    ) * LB + col]);
                    b[j][1] = frag<CVTB>(bp[(kc + 4) * LB + col]);
                }
            }
            #pragma unroll
            for (int i = 0; i < MT; ++i)
                #pragma unroll
                for (int j = 0; j < NT; ++j)
                    mma_tf32(acc[i][j], a[i], b[j]);
        }
        __syncthreads();
    }

    // ---- epilogue ----
    #pragma unroll
    for (int i = 0; i < MT; ++i) {
        const int rloc = wm * WM + i * 16 + lr;
        const float iv0 = NORM ? inv_s[rloc]     : 1.0f;
        const float iv1 = NORM ? inv_s[rloc + 8] : 1.0f;
        #pragma unroll
        for (int j = 0; j < NT; ++j) {
            const int rr = m0 + rloc;
            const int cc = n0 + wn * WN + j * 8 + 2 * lc;
            const float b0 = bias ? bias[cc] : 0.0f;
            const float b1 = bias ? bias[cc + 1] : 0.0f;
            float2 v0 = make_float2(acc[i][j][0] * scale * iv0 + b0,
                                    acc[i][j][1] * scale * iv0 + b1);
            float2 v1 = make_float2(acc[i][j][2] * scale * iv1 + b0,
                                    acc[i][j][3] * scale * iv1 + b1);
            if (OUTMODE != 0) {   // scratch consumed by tf32 MMAs: pre-round
                v0.x = f2tf32(v0.x); v0.y = f2tf32(v0.y);
                v1.x = f2tf32(v1.x); v1.y = f2tf32(v1.y);
            }
            #pragma unroll
            for (int h = 0; h < 2; ++h) {
                const int m = rr + h * 8;
                const float2 v = h ? v1 : v0;
                float* dst;
                if (OUTMODE == 1) {
                    const int bb = m / S_, ss = m % S_;
                    const int hh = cc / HD_, dd = cc % HD_;
                    dst = C + (((long)(bb * NH_ + hh) * S_ + ss) * HD_ + dd);
                } else if (OUTMODE == 2) {
                    dst = C + ((long)(z >> 3) * ((long)S_ * H_)
                              + (long)(z & 7) * HD_ + (long)m * H_ + cc);
                } else {
                    dst = C + ((long)m * ldc + cc);
                }
                *(float2*)dst = v;
            }
        }
    }
}

// ---------------------------------------------------------------------------
// kernel_launch
// Inputs: query, key, value, Wq, bq, Wk, bk, Wv, bv, Wo, bo
// Output: [ x (B*S*H) | attention (B*NH*S*S) ]
// ---------------------------------------------------------------------------
extern "C" void kernel_launch(void* const* d_in, const int* in_sizes, int n_in,
                              void* d_out, int out_size)
{
    const float* query = (const float*)d_in[0];
    const float* key_  = (const float*)d_in[1];
    const float* value = (const float*)d_in[2];
    const float* Wq = (const float*)d_in[3];
    const float* bq = (const float*)d_in[4];
    const float* Wk = (const float*)d_in[5];
    const float* bk = (const float*)d_in[6];
    const float* Wv = (const float*)d_in[7];
    const float* bv = (const float*)d_in[8];
    const float* Wo = (const float*)d_in[9];
    const float* bo = (const float*)d_in[10];

    float* xout = (float*)d_out;

    float *Qp, *Kp, *Vp, *Cp, *Pp, *Afb;
    cudaGetSymbolAddress((void**)&Qp, g_Q);
    cudaGetSymbolAddress((void**)&Kp, g_K);
    cudaGetSymbolAddress((void**)&Vp, g_V);
    cudaGetSymbolAddress((void**)&Cp, g_ctx);
    cudaGetSymbolAddress((void**)&Pp, g_psum);
    cudaGetSymbolAddress((void**)&Afb, g_attn_fb);

    float* attn = ((long)out_size >= (long)XSZ + ASZ) ? (xout + XSZ) : Afb;

    // dynamic smem sizes
    const int SM_BNT = 2 * (128 * 36 + 128 * 36) * 4;          // 73728
    const int SM_AV  = (2 * 128 * 36 + 2 * 32 * 72) * 4;       // 55296
    const int SM_EN  = (128 + 256) * 68 * 4;                   // 104448

    auto proj = gemm_db<128, 128, 32, 64, true, 1, false, true, true, true>;
    auto oprj = gemm_db<128, 128, 32, 64, true, 0, false, false, true, false>;
    auto avk  = gemm_db<128,  64, 32, 32, false, 2, true, true, false, false>;

    cudaFuncSetAttribute(proj, cudaFuncAttributeMaxDynamicSharedMemorySize, SM_BNT);
    cudaFuncSetAttribute(oprj, cudaFuncAttributeMaxDynamicSharedMemorySize, SM_BNT);
    cudaFuncSetAttribute(avk,  cudaFuncAttributeMaxDynamicSharedMemorySize, SM_AV);
    cudaFuncSetAttribute(energy_tc, cudaFuncAttributeMaxDynamicSharedMemorySize, SM_EN);

    const dim3 blk(256);
    const PtrSet P0{query, Wq, bq, Qp};
    const PtrSet P1{key_,  Wk, bk, Kp};
    const PtrSet P2{value, Wv, bv, Vp};
    const PtrSet PO{Cp,    Wo, bo, xout};
    const PtrSet PA{attn,  Vp, nullptr, Cp};
    const PtrSet PN{nullptr, nullptr, nullptr, nullptr};

    // Q/K/V projections merged into ONE launch (z selects the pointer set)
    proj<<<dim3(H_ / 128, (B_ * S_) / 128, 3), blk, SM_BNT>>>(
        P0, P1, P2, nullptr, nullptr, H_, H_, H_, 0, 0, 0, 0, 1.0f);

    // energy + exp (unnormalized) + row partial sums, n-walk of 8 tiles,
    // j-pipelined epilogue
    energy_tc<<<dim3(S_ / (128 * NWALK), S_ / 128, B_ * NH_), blk, SM_EN>>>(
        Qp, Kp, attn, Pp);

    // ctx = softmax(attn) @ V; writes normalized attention back in place
    avk<<<dim3(1, S_ / 128, B_ * NH_), blk, SM_AV>>>(
        PA, PN, PN, Pp, attn, S_, S_, HD_, 0,
        (long)S_ * S_, (long)S_ * HD_, 0, 1.0f);

    // x = ctx @ Wo^T + bo -> d_out (NT)
    oprj<<<dim3(H_ / 128, (B_ * S_) / 128, 1), blk, SM_BNT>>>(
        PO, PN, PN, nullptr, nullptr, H_, H_, H_, H_, 0, 0, 0, 1.0f);
}